// round 14
// baseline (speedup 1.0000x reference)
#include <cuda_runtime.h>
#include <cuda_bf16.h>
#include <math.h>

#define NN 50000
#define NE 1000000
#define HH 128

__device__ float g_x[NN * HH];
__device__ float g_xm[NN * HH];
__device__ float g_agg[NN * HH];
__device__ int g_ncnt, g_fcnt;
__device__ int2 g_nJI[NE];
__device__ int2 g_fJI[NE];
// pre-split weights (bf16 hi/lo, pitch 136)
__device__ __nv_bfloat16 g_WeH[128 * 136], g_WeL[128 * 136];
__device__ __nv_bfloat16 g_WfH[16 * 136],  g_WfL[16 * 136];
__device__ __nv_bfloat16 g_WmH[128 * 136], g_WmL[128 * 136];
__device__ __nv_bfloat16 g_WuH[128 * 136], g_WuL[128 * 136];
__device__ __nv_bfloat16 g_WoH[128 * 136], g_WoL[128 * 136];

__device__ __forceinline__ float swishf(float v) { return v / (1.f + expf(-v)); }

struct F3 { float x, y, z; };
__device__ __forceinline__ F3 mk3(float a, float b, float c) { F3 r; r.x=a; r.y=b; r.z=c; return r; }
__device__ __forceinline__ F3 sub3(F3 a, F3 b) { return mk3(a.x-b.x, a.y-b.y, a.z-b.z); }
__device__ __forceinline__ F3 crs3(F3 a, F3 b) {
    return mk3(a.y*b.z - a.z*b.y, a.z*b.x - a.x*b.z, a.x*b.y - a.y*b.x);
}
__device__ __forceinline__ float dot3(F3 a, F3 b) { return a.x*b.x + a.y*b.y + a.z*b.z; }
__device__ __forceinline__ F3 ld3(const float* __restrict__ p, int i) {
    return mk3(p[3*i], p[3*i+1], p[3*i+2]);
}
__device__ __forceinline__ unsigned sptr(const void* p) {
    return (unsigned)__cvta_generic_to_shared(p);
}
__device__ __forceinline__ void split2(float x0, float x1, __nv_bfloat162& h, __nv_bfloat162& l) {
    __nv_bfloat16 h0 = __float2bfloat16_rn(x0);
    __nv_bfloat16 h1 = __float2bfloat16_rn(x1);
    h = __halves2bfloat162(h0, h1);
    l = __halves2bfloat162(__float2bfloat16_rn(x0 - __bfloat162float(h0)),
                           __float2bfloat16_rn(x1 - __bfloat162float(h1)));
}
__device__ __forceinline__ void split1(float x, __nv_bfloat16* pH, __nv_bfloat16* pL) {
    __nv_bfloat16 h = __float2bfloat16_rn(x);
    *pH = h;
    *pL = __float2bfloat16_rn(x - __bfloat162float(h));
}
// radial basis via Chebyshev recurrence
__device__ __forceinline__ void radial6(float u, float dist, float* r) {
    float s1, c1;
    sincosf(3.14159274f * u, &s1, &c1);
    float fc = 0.5f * (c1 + 1.f);
    float rs = (float)0.41702882811414954 * fc / (dist + 1e-6f);
    float two_c = 2.f * c1;
    float sm = 0.f, sn = s1;
    r[0] = rs * sn;
    #pragma unroll
    for (int n = 1; n < 6; n++) {
        float sx = two_c * sn - sm;
        sm = sn; sn = sx;
        r[n] = rs * sx;
    }
}

// per-edge prefetched data (role-dependent payload in x0..x3)
struct EdgeData { int j, i, jv; F3 pi, pj, x0, x1, x2, x3; };
__device__ __forceinline__ void load_edge_near(int idx, int cnt, int role,
                                               const float* __restrict__ pos,
                                               const float* __restrict__ posn,
                                               const float* __restrict__ posc,
                                               EdgeData& d) {
    bool valid = idx < cnt;
    int2 ji = g_nJI[valid ? idx : cnt - 1];
    d.j = ji.x; d.i = ji.y;
    d.jv = valid ? ji.x : -1;
    d.pi = ld3(pos, d.i);
    d.pj = ld3(pos, d.j);
    if (role == 0) {
        int r0 = (d.i == 0) ? NN - 1 : d.i - 1;
        int r1 = (d.i == NN - 1) ? 0 : d.i + 1;
        d.x0 = ld3(pos, r0);
        d.x1 = ld3(pos, r1);
    } else {
        d.x0 = ld3(posn, d.i);
        d.x1 = ld3(posc, d.i);
        d.x2 = ld3(posn, d.j);
        d.x3 = ld3(posc, d.j);
    }
}

#define LDSM4(r0,r1,r2,r3,addr) \
    asm volatile("ldmatrix.sync.aligned.m8n8.x4.shared.b16 {%0,%1,%2,%3},[%4];" \
                 : "=r"(r0),"=r"(r1),"=r"(r2),"=r"(r3) : "r"(addr))
#define LDSM4T(r0,r1,r2,r3,addr) \
    asm volatile("ldmatrix.sync.aligned.m8n8.x4.trans.shared.b16 {%0,%1,%2,%3},[%4];" \
                 : "=r"(r0),"=r"(r1),"=r"(r2),"=r"(r3) : "r"(addr))
#define MMA16816(d,a0,a1,a2,a3,b0,b1) \
    asm volatile("mma.sync.aligned.m16n8k16.row.col.f32.bf16.bf16.f32 " \
                 "{%0,%1,%2,%3},{%4,%5,%6,%7},{%8,%9},{%0,%1,%2,%3};" \
                 : "+f"(d[0]),"+f"(d[1]),"+f"(d[2]),"+f"(d[3]) \
                 : "r"(a0),"r"(a1),"r"(a2),"r"(a3),"r"(b0),"r"(b1))

__global__ void k_zero() {
    int i = blockIdx.x * 256 + threadIdx.x;
    ((float4*)g_agg)[i] = make_float4(0.f, 0.f, 0.f, 0.f);
    if (i == 0) { g_ncnt = 0; g_fcnt = 0; }
}

__global__ void k_splitW(const float* __restrict__ We, const float* __restrict__ Wm,
                         const float* __restrict__ Wu, const float* __restrict__ Wo) {
    int b = blockIdx.x, tid = threadIdx.x;
    if (b < 128) {
        float v = (b < 124) ? We[b * 128 + tid] : 0.f;
        split1(v, g_WeH + b * 136 + tid, g_WeL + b * 136 + tid);
    } else if (b < 256) {
        int r = b - 128;
        split1(Wm[r * 128 + tid], g_WmH + r * 136 + tid, g_WmL + r * 136 + tid);
    } else if (b < 384) {
        int r = b - 256;
        split1(Wu[r * 128 + tid], g_WuH + r * 136 + tid, g_WuL + r * 136 + tid);
    } else if (b < 512) {
        int r = b - 384;
        split1(Wo[r * 128 + tid], g_WoH + r * 136 + tid, g_WoL + r * 136 + tid);
    } else {
        int r = b - 512;
        split1(We[(108 + r) * 128 + tid], g_WfH + r * 136 + tid, g_WfL + r * 136 + tid);
    }
}

__global__ void k_classify(const int* __restrict__ ei, const float* __restrict__ pos) {
    int e = blockIdx.x * 256 + threadIdx.x;
    bool valid = e < NE;
    int ee = valid ? e : NE - 1;
    int j = ei[ee], i = ei[NE + ee];
    F3 d = sub3(ld3(pos, j), ld3(pos, i));
    float dist = sqrtf(dot3(d, d));
    bool far_ = valid && ((dist / 11.5f) >= 1.f);
    bool near_ = valid && !far_;
    int lane = threadIdx.x & 31;
    unsigned bf = __ballot_sync(0xffffffffu, far_);
    unsigned bn = __ballot_sync(0xffffffffu, near_);
    if (bf) {
        int src = __ffs(bf) - 1;
        int base = 0;
        if (lane == src) base = atomicAdd(&g_fcnt, __popc(bf));
        base = __shfl_sync(0xffffffffu, base, src);
        if (far_) g_fJI[base + __popc(bf & ((1u << lane) - 1))] = make_int2(j, i);
    }
    if (bn) {
        int src = __ffs(bn) - 1;
        int base = 0;
        if (lane == src) base = atomicAdd(&g_ncnt, __popc(bn));
        base = __shfl_sync(0xffffffffu, base, src);
        if (near_) g_nJI[base + __popc(bn & ((1u << lane) - 1))] = make_int2(j, i);
    }
}

__global__ void __launch_bounds__(256) k_embed(const int* __restrict__ z,
                                               const float* __restrict__ bb,
                                               const float* __restrict__ sc,
                                               const float* __restrict__ W,
                                               const float* __restrict__ b) {
    __shared__ float sW[40 * 64];
    __shared__ float sb[64];
    int tid = threadIdx.x;
    for (int idx = tid; idx < 40 * 64; idx += 256) sW[idx] = W[idx];
    if (tid < 64) sb[tid] = b[tid];
    __syncthreads();
    int node = blockIdx.x * 32 + (tid >> 3);
    int c0 = (tid & 7) * 8;
    if (node < NN) {
        float acc[8];
        int zz = z[node];
        #pragma unroll
        for (int cc = 0; cc < 8; cc++) acc[cc] = sb[c0 + cc] + sW[zz * 64 + c0 + cc];
        #pragma unroll
        for (int q = 0; q < 6; q++) {
            float v = bb[node * 6 + q];
            #pragma unroll
            for (int cc = 0; cc < 8; cc++) acc[cc] += v * sW[(26 + q) * 64 + c0 + cc];
        }
        #pragma unroll
        for (int q = 0; q < 8; q++) {
            float v = sc[node * 8 + q];
            #pragma unroll
            for (int cc = 0; cc < 8; cc++) acc[cc] += v * sW[(32 + q) * 64 + c0 + cc];
        }
        float* o = g_x + node * HH + c0;
        *(float4*)o = make_float4(acc[0], acc[1], acc[2], acc[3]);
        *(float4*)(o + 4) = make_float4(acc[4], acc[5], acc[6], acc[7]);
    }
}

__global__ void __launch_bounds__(256) k_esm_tc(const float* __restrict__ esm,
                                                const float* __restrict__ W,
                                                const float* __restrict__ b) {
    __shared__ __nv_bfloat16 AsH[128 * 40];
    __shared__ __nv_bfloat16 AsL[128 * 40];
    __shared__ __nv_bfloat16 BsH[32 * 72];
    __shared__ __nv_bfloat16 BsL[32 * 72];
    int tid = threadIdx.x;
    int m0 = blockIdx.x * 128;
    int wid = tid >> 5, lane = tid & 31;
    int warp_m = wid & 3, warp_n = wid >> 2;
    int arow = tid >> 1, ahalf = tid & 1;
    int grow = m0 + arow; if (grow >= NN) grow = NN - 1;
    const float* aptr = esm + (size_t)grow * 1280 + ahalf * 16;
    int brow = tid >> 3, bcol = (tid & 7) * 8;
    const float* bptr = W + brow * 64 + bcol;
    float acc[2][4][4];
    #pragma unroll
    for (int a_ = 0; a_ < 2; a_++)
        #pragma unroll
        for (int b_ = 0; b_ < 4; b_++)
            #pragma unroll
            for (int q = 0; q < 4; q++) acc[a_][b_][q] = 0.f;
    float4 ra[4]; float4 rb[2];
    #pragma unroll
    for (int q = 0; q < 4; q++) ra[q] = *(const float4*)(aptr + q * 4);
    rb[0] = *(const float4*)bptr; rb[1] = *(const float4*)(bptr + 4);
    int a_r = lane & 15, a_c = (lane >> 4) * 8;
    int b_k = lane & 15, b_n = (lane >> 4) * 8;
    for (int c = 0; c < 40; c++) {
        {
            float av[16] = {ra[0].x, ra[0].y, ra[0].z, ra[0].w,
                            ra[1].x, ra[1].y, ra[1].z, ra[1].w,
                            ra[2].x, ra[2].y, ra[2].z, ra[2].w,
                            ra[3].x, ra[3].y, ra[3].z, ra[3].w};
            __nv_bfloat162* dH = (__nv_bfloat162*)(AsH + arow * 40 + ahalf * 16);
            __nv_bfloat162* dL = (__nv_bfloat162*)(AsL + arow * 40 + ahalf * 16);
            #pragma unroll
            for (int q = 0; q < 8; q++) {
                __nv_bfloat162 h, l;
                split2(av[2 * q], av[2 * q + 1], h, l);
                dH[q] = h; dL[q] = l;
            }
            float bv[8] = {rb[0].x, rb[0].y, rb[0].z, rb[0].w,
                           rb[1].x, rb[1].y, rb[1].z, rb[1].w};
            __nv_bfloat162* eH = (__nv_bfloat162*)(BsH + brow * 72 + bcol);
            __nv_bfloat162* eL = (__nv_bfloat162*)(BsL + brow * 72 + bcol);
            #pragma unroll
            for (int q = 0; q < 4; q++) {
                __nv_bfloat162 h, l;
                split2(bv[2 * q], bv[2 * q + 1], h, l);
                eH[q] = h; eL[q] = l;
            }
        }
        __syncthreads();
        if (c < 39) {
            aptr += 32; bptr += 32 * 64;
            #pragma unroll
            for (int q = 0; q < 4; q++) ra[q] = *(const float4*)(aptr + q * 4);
            rb[0] = *(const float4*)bptr; rb[1] = *(const float4*)(bptr + 4);
        }
        #pragma unroll
        for (int ks = 0; ks < 2; ks++) {
            unsigned ah[2][4], al[2][4], bh[2][4], bl[2][4];
            #pragma unroll
            for (int mt = 0; mt < 2; mt++) {
                int row = warp_m * 32 + mt * 16 + a_r;
                int col = ks * 16 + a_c;
                LDSM4(ah[mt][0], ah[mt][1], ah[mt][2], ah[mt][3], sptr(AsH + row * 40 + col));
                LDSM4(al[mt][0], al[mt][1], al[mt][2], al[mt][3], sptr(AsL + row * 40 + col));
            }
            #pragma unroll
            for (int g = 0; g < 2; g++) {
                int kk = ks * 16 + b_k;
                int nn = warp_n * 32 + g * 16 + b_n;
                LDSM4T(bh[g][0], bh[g][1], bh[g][2], bh[g][3], sptr(BsH + kk * 72 + nn));
                LDSM4T(bl[g][0], bl[g][1], bl[g][2], bl[g][3], sptr(BsL + kk * 72 + nn));
            }
            #pragma unroll
            for (int mt = 0; mt < 2; mt++)
                #pragma unroll
                for (int nt = 0; nt < 4; nt++) {
                    int g = nt >> 1, h = (nt & 1) * 2;
                    MMA16816(acc[mt][nt], ah[mt][0], ah[mt][1], ah[mt][2], ah[mt][3],
                             bh[g][h], bh[g][h + 1]);
                    MMA16816(acc[mt][nt], ah[mt][0], ah[mt][1], ah[mt][2], ah[mt][3],
                             bl[g][h], bl[g][h + 1]);
                    MMA16816(acc[mt][nt], al[mt][0], al[mt][1], al[mt][2], al[mt][3],
                             bh[g][h], bh[g][h + 1]);
                }
        }
        __syncthreads();
    }
    #pragma unroll
    for (int mt = 0; mt < 2; mt++)
        #pragma unroll
        for (int nt = 0; nt < 4; nt++) {
            int row = m0 + warp_m * 32 + mt * 16 + (lane >> 2);
            int col = warp_n * 32 + nt * 8 + (lane & 3) * 2;
            if (row < NN) {
                g_x[row * HH + 64 + col] = acc[mt][nt][0] + b[col];
                g_x[row * HH + 64 + col + 1] = acc[mt][nt][1] + b[col + 1];
            }
            if (row + 8 < NN) {
                g_x[(row + 8) * HH + 64 + col] = acc[mt][nt][2] + b[col];
                g_x[(row + 8) * HH + 64 + col + 1] = acc[mt][nt][3] + b[col + 1];
            }
        }
}

template <int EPI>
__global__ void __launch_bounds__(256) k_gemm128_tc(const float* __restrict__ bias) {
    extern __shared__ __align__(16) char smraw[];
    __nv_bfloat16* AsH = (__nv_bfloat16*)smraw;
    __nv_bfloat16* AsL = AsH + 128 * 136;
    __nv_bfloat16* BsH = AsL + 128 * 136;
    __nv_bfloat16* BsL = BsH + 128 * 136;
    int tid = threadIdx.x;
    int m0 = blockIdx.x * 128;
    int wid = tid >> 5, lane = tid & 31;
    int warp_m = wid & 3, warp_n = wid >> 2;
    const float* A = (EPI == 0) ? g_x : (EPI == 1) ? g_agg : g_xm;
    float* O = (EPI == 2) ? g_agg : g_xm;
    const __nv_bfloat16* WH = (EPI == 0) ? g_WmH : (EPI == 1) ? g_WuH : g_WoH;
    const __nv_bfloat16* WL = (EPI == 0) ? g_WmL : (EPI == 1) ? g_WuL : g_WoL;
    {
        const uint4* sH = (const uint4*)WH;
        const uint4* sL = (const uint4*)WL;
        uint4* dH = (uint4*)BsH;
        uint4* dL = (uint4*)BsL;
        for (int idx = tid; idx < 2176; idx += 256) { dH[idx] = sH[idx]; dL[idx] = sL[idx]; }
    }
    {
        int row = tid >> 1, half = tid & 1;
        int grow = m0 + row; if (grow >= NN) grow = NN - 1;
        const float* ap = A + grow * HH + half * 64;
        __nv_bfloat162* dH = (__nv_bfloat162*)(AsH + row * 136 + half * 64);
        __nv_bfloat162* dL = (__nv_bfloat162*)(AsL + row * 136 + half * 64);
        #pragma unroll
        for (int q = 0; q < 16; q++) {
            float4 v = ((const float4*)ap)[q];
            __nv_bfloat162 h, l;
            split2(v.x, v.y, h, l); dH[2 * q] = h; dL[2 * q] = l;
            split2(v.z, v.w, h, l); dH[2 * q + 1] = h; dL[2 * q + 1] = l;
        }
    }
    __syncthreads();
    float acc[2][8][4];
    #pragma unroll
    for (int a_ = 0; a_ < 2; a_++)
        #pragma unroll
        for (int b_ = 0; b_ < 8; b_++)
            #pragma unroll
            for (int q = 0; q < 4; q++) acc[a_][b_][q] = 0.f;
    int a_r = lane & 15, a_c = (lane >> 4) * 8;
    int b_k = lane & 15, b_n = (lane >> 4) * 8;
    #pragma unroll
    for (int ks = 0; ks < 8; ks++) {
        unsigned ah[2][4], al[2][4];
        #pragma unroll
        for (int mt = 0; mt < 2; mt++) {
            int row = warp_m * 32 + mt * 16 + a_r;
            int col = ks * 16 + a_c;
            LDSM4(ah[mt][0], ah[mt][1], ah[mt][2], ah[mt][3], sptr(AsH + row * 136 + col));
            LDSM4(al[mt][0], al[mt][1], al[mt][2], al[mt][3], sptr(AsL + row * 136 + col));
        }
        #pragma unroll
        for (int g = 0; g < 4; g++) {
            unsigned bh[4], bl[4];
            int kk = ks * 16 + b_k;
            int nn = warp_n * 64 + g * 16 + b_n;
            LDSM4T(bh[0], bh[1], bh[2], bh[3], sptr(BsH + kk * 136 + nn));
            LDSM4T(bl[0], bl[1], bl[2], bl[3], sptr(BsL + kk * 136 + nn));
            #pragma unroll
            for (int mt = 0; mt < 2; mt++)
                #pragma unroll
                for (int t8 = 0; t8 < 2; t8++) {
                    int h = t8 * 2;
                    float* d = acc[mt][g * 2 + t8];
                    MMA16816(d, ah[mt][0], ah[mt][1], ah[mt][2], ah[mt][3], bh[h], bh[h + 1]);
                    MMA16816(d, ah[mt][0], ah[mt][1], ah[mt][2], ah[mt][3], bl[h], bl[h + 1]);
                    MMA16816(d, al[mt][0], al[mt][1], al[mt][2], al[mt][3], bh[h], bh[h + 1]);
                }
        }
    }
    #pragma unroll
    for (int mt = 0; mt < 2; mt++)
        #pragma unroll
        for (int nt = 0; nt < 8; nt++) {
            int row = m0 + warp_m * 32 + mt * 16 + (lane >> 2);
            int col = warp_n * 64 + nt * 8 + (lane & 3) * 2;
            float* d = acc[mt][nt];
            #pragma unroll
            for (int rr = 0; rr < 2; rr++) {
                int r = row + rr * 8;
                if (r < NN) {
                    float v0 = d[rr * 2], v1 = d[rr * 2 + 1];
                    float o0, o1;
                    if (EPI == 2) {
                        o0 = fmaxf(v0 + bias[col], 0.f);
                        o1 = fmaxf(v1 + bias[col + 1], 0.f);
                    } else if (EPI == 1) {
                        float2 xv = *(const float2*)(g_x + r * HH + col);
                        o0 = xv.x + swishf(v0);
                        o1 = xv.y + swishf(v1);
                    } else {
                        o0 = swishf(v0);
                        o1 = swishf(v1);
                    }
                    *(float2*)(O + r * HH + col) = make_float2(o0, o1);
                }
            }
        }
}

__device__ __forceinline__ void edge_scatter(float acc[2][8][4], const int* js, const int* is_,
                                             int warp_m, int warp_n, int lane) {
    #pragma unroll
    for (int mt = 0; mt < 2; mt++)
        #pragma unroll
        for (int nt = 0; nt < 8; nt++) {
            int el = warp_m * 32 + mt * 16 + (lane >> 2);
            int col = warp_n * 64 + nt * 8 + (lane & 3) * 2;
            float* d = acc[mt][nt];
            #pragma unroll
            for (int rr = 0; rr < 2; rr++) {
                int e = el + rr * 8;
                int j = js[e];
                if (j >= 0) {
                    int i = is_[e];
                    float2 xv = *(const float2*)(g_xm + j * HH + col);
                    float m0 = swishf(d[rr * 2]) * xv.x;
                    float m1 = swishf(d[rr * 2 + 1]) * xv.y;
                    asm volatile("red.global.add.v2.f32 [%0], {%1,%2};"
                                 :: "l"(g_agg + i * HH + col), "f"(m0), "f"(m1) : "memory");
                }
            }
        }
}

// feature computation from prefetched register data
__device__ __forceinline__ void near_features(const EdgeData& d, int role,
                                              const float* freqs,
                                              __nv_bfloat16* fH, __nv_bfloat16* fL) {
    F3 vji = sub3(d.pj, d.pi);
    float dist = sqrtf(dot3(vji, vji));
    float u = fminf(dist / 11.5f, 1.f);
    float r[6];
    radial6(u, dist, r);
    if (role == 0) {
        F3 vr0 = sub3(d.x0, d.pi);
        F3 vr1 = sub3(d.x1, d.pi);
        float a = dot3(vji, vr0);
        F3 cr = crs3(vji, vr0);
        float b2 = dot3(cr, cr);
        float ct1 = a * rsqrtf(fmaxf(a * a + b2, 1e-30f));
        float ct2 = 2.f * ct1 * ct1 - 1.f;
        F3 p1 = crs3(vr0, vr1), p2 = crs3(vr0, vji);
        float ap = dot3(p1, p2);
        F3 c12 = crs3(p1, p2);
        float bp = dot3(c12, vr0) / (sqrtf(dot3(vr0, vr0)) + 1e-7f);
        float cp1 = ap * rsqrtf(fmaxf(ap * ap + bp * bp, 1e-30f));
        float cp2 = 2.f * cp1 * cp1 - 1.f;
        float ct[3] = {1.f, ct1, ct2};
        float cp[3] = {1.f, cp1, cp2};
        #pragma unroll
        for (int n = 0; n < 6; n++)
            #pragma unroll
            for (int l = 0; l < 3; l++) {
                float rl = r[n] * ct[l];
                #pragma unroll
                for (int m = 0; m < 3; m++) {
                    int k = n * 9 + l * 3 + m;
                    split1(rl * cp[m], fH + k, fL + k);
                }
            }
        float dpe = (float)(d.j - d.i);
        #pragma unroll
        for (int kk = 0; kk < 8; kk++) {
            float s, c;
            sincosf(dpe * freqs[kk], &s, &c);
            split1(c, fH + 108 + kk, fL + 108 + kk);
            split1(s, fH + 116 + kk, fL + 116 + kk);
        }
    } else {
        F3 o1x = sub3(d.x0, d.pi);
        F3 o1z = crs3(o1x, crs3(o1x, sub3(d.x1, d.pi)));
        float o1zl = sqrtf(dot3(o1z, o1z)) + 1e-7f;
        F3 o2x = sub3(d.x2, d.pj);
        F3 o2z = crs3(o2x, crs3(o2x, sub3(d.x3, d.pj)));
        float o2zl = sqrtf(dot3(o2z, o2z)) + 1e-7f;
        F3 nv = crs3(o1z, o2z);
        float a1 = dot3(o1x, nv);
        float b1 = dot3(crs3(o1x, nv), o1z) / o1zl;
        float cA10 = a1 * rsqrtf(fmaxf(a1 * a1 + b1 * b1, 1e-30f));
        float cA11 = 2.f * cA10 * cA10 - 1.f;
        float a2 = dot3(o1z, o2z);
        float b2v = sqrtf(dot3(nv, nv));
        float cA20 = a2 * rsqrtf(fmaxf(a2 * a2 + b2v * b2v, 1e-30f));
        float cA21 = 2.f * cA20 * cA20 - 1.f;
        float a3 = dot3(nv, o2x);
        float b3 = dot3(crs3(nv, o2x), o2z) / o2zl;
        float cA30 = a3 * rsqrtf(fmaxf(a3 * a3 + b3 * b3, 1e-30f));
        float cA31 = 2.f * cA30 * cA30 - 1.f;
        float cA[3][3] = {{1.f, cA10, cA11}, {1.f, cA20, cA21}, {1.f, cA30, cA31}};
        #pragma unroll
        for (int t = 0; t < 3; t++)
            #pragma unroll
            for (int n = 0; n < 6; n++)
                #pragma unroll
                for (int l = 0; l < 3; l++) {
                    int k = 54 + t * 18 + n * 3 + l;
                    split1(r[n] * cA[t][l], fH + k, fL + k);
                }
        __nv_bfloat16 zb = __float2bfloat16_rn(0.f);
        #pragma unroll
        for (int k = 124; k < 128; k++) { fH[k] = zb; fL[k] = zb; }
    }
}

// near edges: persistent, prefetch next tile's gathers during mma
__global__ void __launch_bounds__(256) k_edge_near_tc(const float* __restrict__ pos,
                                                      const float* __restrict__ posn,
                                                      const float* __restrict__ posc) {
    int cnt = g_ncnt;
    extern __shared__ __align__(16) char smraw[];
    __nv_bfloat16* WsH = (__nv_bfloat16*)smraw;
    __nv_bfloat16* WsL = WsH + 128 * 136;
    __nv_bfloat16* FsH = WsL + 128 * 136;
    __nv_bfloat16* FsL = FsH + 128 * 136;
    int* js = (int*)(FsL + 128 * 136);
    int* is_ = js + 128;
    float* freqs = (float*)(is_ + 128);
    int tid = threadIdx.x;
    int wid = tid >> 5, lane = tid & 31;
    int warp_m = wid & 3, warp_n = wid >> 2;
    int e = tid & 127, role = tid >> 7;

    {
        const uint4* sH = (const uint4*)g_WeH;
        const uint4* sL = (const uint4*)g_WeL;
        uint4* dH = (uint4*)WsH;
        uint4* dL = (uint4*)WsL;
        for (int idx = tid; idx < 2176; idx += 256) { dH[idx] = sH[idx]; dL[idx] = sL[idx]; }
    }
    if (tid < 8) {
        float t = (float)(2 * tid) * (float)(-0.5756462732485115);
        freqs[tid] = (float)exp((double)t);
    }

    int a_r = lane & 15, a_c = (lane >> 4) * 8;
    int b_k = lane & 15, b_n = (lane >> 4) * 8;
    int stride = gridDim.x * 128;

    EdgeData cur;
    int t0 = blockIdx.x * 128;
    if (t0 < cnt) load_edge_near(t0 + e, cnt, role, pos, posn, posc, cur);

    for (; t0 < cnt; t0 += stride) {
        __syncthreads();   // prev-iter LDSM reads of Fs done; W staged (iter 0)
        if (role == 0) { js[e] = cur.jv; is_[e] = cur.i; }
        near_features(cur, role, freqs, FsH + e * 136, FsL + e * 136);
        __syncthreads();
        // prefetch next tile while mma runs
        int nt0 = t0 + stride;
        if (nt0 < cnt) load_edge_near(nt0 + e, cnt, role, pos, posn, posc, cur);

        float acc[2][8][4];
        #pragma unroll
        for (int a_ = 0; a_ < 2; a_++)
            #pragma unroll
            for (int b_ = 0; b_ < 8; b_++)
                #pragma unroll
                for (int q = 0; q < 4; q++) acc[a_][b_][q] = 0.f;
        #pragma unroll
        for (int ks = 0; ks < 8; ks++) {
            unsigned ah[2][4], al[2][4];
            #pragma unroll
            for (int mt = 0; mt < 2; mt++) {
                int row = warp_m * 32 + mt * 16 + a_r;
                int col = ks * 16 + a_c;
                LDSM4(ah[mt][0], ah[mt][1], ah[mt][2], ah[mt][3], sptr(FsH + row * 136 + col));
                LDSM4(al[mt][0], al[mt][1], al[mt][2], al[mt][3], sptr(FsL + row * 136 + col));
            }
            #pragma unroll
            for (int g = 0; g < 4; g++) {
                unsigned bh[4], bl[4];
                int kk = ks * 16 + b_k;
                int nn = warp_n * 64 + g * 16 + b_n;
                LDSM4T(bh[0], bh[1], bh[2], bh[3], sptr(WsH + kk * 136 + nn));
                LDSM4T(bl[0], bl[1], bl[2], bl[3], sptr(WsL + kk * 136 + nn));
                #pragma unroll
                for (int mt = 0; mt < 2; mt++)
                    #pragma unroll
                    for (int t8 = 0; t8 < 2; t8++) {
                        int h = t8 * 2;
                        float* d = acc[mt][g * 2 + t8];
                        MMA16816(d, ah[mt][0], ah[mt][1], ah[mt][2], ah[mt][3], bh[h], bh[h + 1]);
                        MMA16816(d, ah[mt][0], ah[mt][1], ah[mt][2], ah[mt][3], bl[h], bl[h + 1]);
                        MMA16816(d, al[mt][0], al[mt][1], al[mt][2], al[mt][3], bh[h], bh[h + 1]);
                    }
            }
        }
        edge_scatter(acc, js, is_, warp_m, warp_n, lane);
    }
}

// far edges: persistent, prefetch next tile's ji during mma
__global__ void __launch_bounds__(256) k_edge_far_tc() {
    int cnt = g_fcnt;
    __shared__ __align__(16) __nv_bfloat16 WsH[16 * 136], WsL[16 * 136];
    __shared__ __align__(16) __nv_bfloat16 FsH[128 * 24], FsL[128 * 24];
    __shared__ int js[128], is_[128];
    __shared__ float freqs[8];
    int tid = threadIdx.x;
    int wid = tid >> 5, lane = tid & 31;
    int warp_m = wid & 3, warp_n = wid >> 2;
    int e = tid & 127, role = tid >> 7;

    {
        const uint4* sH = (const uint4*)g_WfH;
        const uint4* sL = (const uint4*)g_WfL;
        uint4* dH = (uint4*)WsH;
        uint4* dL = (uint4*)WsL;
        for (int idx = tid; idx < 272; idx += 256) { dH[idx] = sH[idx]; dL[idx] = sL[idx]; }
    }
    if (tid < 8) {
        float t = (float)(2 * tid) * (float)(-0.5756462732485115);
        freqs[tid] = (float)exp((double)t);
    }

    int a_r = lane & 15, a_c = (lane >> 4) * 8;
    int b_k = lane & 15, b_n = (lane >> 4) * 8;
    int stride = gridDim.x * 128;

    int2 cur; bool curv = false;
    int t0 = blockIdx.x * 128;
    if (t0 < cnt) {
        int idx = t0 + e;
        curv = idx < cnt;
        cur = g_fJI[curv ? idx : cnt - 1];
    }

    for (; t0 < cnt; t0 += stride) {
        __syncthreads();
        {
            if (role == 0) { js[e] = curv ? cur.x : -1; is_[e] = cur.y; }
            float dpe = (float)(cur.x - cur.y);
            __nv_bfloat16* fH = FsH + e * 24;
            __nv_bfloat16* fL = FsL + e * 24;
            #pragma unroll
            for (int q = 0; q < 4; q++) {
                int kk = role * 4 + q;
                float s, c;
                sincosf(dpe * freqs[kk], &s, &c);
                split1(c, fH + kk, fL + kk);
                split1(s, fH + 8 + kk, fL + 8 + kk);
            }
        }
        __syncthreads();
        int nt0 = t0 + stride;
        if (nt0 < cnt) {
            int idx = nt0 + e;
            curv = idx < cnt;
            cur = g_fJI[curv ? idx : cnt - 1];
        }

        float acc[2][8][4];
        #pragma unroll
        for (int a_ = 0; a_ < 2; a_++)
            #pragma unroll
            for (int b_ = 0; b_ < 8; b_++)
                #pragma unroll
                for (int q = 0; q < 4; q++) acc[a_][b_][q] = 0.f;
        unsigned ah[2][4], al[2][4];
        #pragma unroll
        for (int mt = 0; mt < 2; mt++) {
            int row = warp_m * 32 + mt * 16 + a_r;
            LDSM4(ah[mt][0], ah[mt][1], ah[mt][2], ah[mt][3], sptr(FsH + row * 24 + a_c));
            LDSM4(al[mt][0], al[mt][1], al[mt][2], al[mt][3], sptr(FsL + row * 24 + a_c));
        }
        #pragma unroll
        for (int g = 0; g < 4; g++) {
            unsigned bh[4], bl[4];
            int nn = warp_n * 64 + g * 16 + b_n;
            LDSM4T(bh[0], bh[1], bh[2], bh[3], sptr(WsH + b_k * 136 + nn));
            LDSM4T(bl[0], bl[1], bl[2], bl[3], sptr(WsL + b_k * 136 + nn));
            #pragma unroll
            for (int mt = 0; mt < 2; mt++)
                #pragma unroll
                for (int t8 = 0; t8 < 2; t8++) {
                    int h = t8 * 2;
                    float* d = acc[mt][g * 2 + t8];
                    MMA16816(d, ah[mt][0], ah[mt][1], ah[mt][2], ah[mt][3], bh[h], bh[h + 1]);
                    MMA16816(d, ah[mt][0], ah[mt][1], ah[mt][2], ah[mt][3], bl[h], bl[h + 1]);
                    MMA16816(d, al[mt][0], al[mt][1], al[mt][2], al[mt][3], bh[h], bh[h + 1]);
                }
        }
        edge_scatter(acc, js, is_, warp_m, warp_n, lane);
    }
}

__global__ void __launch_bounds__(256) k_nodehead(const float* __restrict__ W0,
                                                  const float* __restrict__ b0,
                                                  const float* __restrict__ Wf,
                                                  const float* __restrict__ bf,
                                                  float* __restrict__ out2) {
    __shared__ float sW[4096];
    __shared__ float sb[32], sWf[64], sbf[2];
    int tid = threadIdx.x;
    for (int idx = tid; idx < 4096; idx += 256) sW[idx] = W0[idx];
    if (tid < 32) sb[tid] = b0[tid];
    if (tid < 64) sWf[tid] = Wf[tid];
    if (tid < 2) sbf[tid] = bf[tid];
    __syncthreads();
    int w = tid >> 5, lane = tid & 31;
    int n = blockIdx.x * 8 + w;
    if (n >= NN) return;
    const float* xr = g_x + n * HH;
    float acc = sb[lane];
    #pragma unroll 8
    for (int k = 0; k < 128; k++) acc += xr[k] * sW[k * 32 + lane];
    float xn = fmaxf(acc, 0.f);
    float v0 = xn * sWf[lane * 2], v1 = xn * sWf[lane * 2 + 1];
    #pragma unroll
    for (int off = 16; off > 0; off >>= 1) {
        v0 += __shfl_xor_sync(0xffffffffu, v0, off);
        v1 += __shfl_xor_sync(0xffffffffu, v1, off);
    }
    if (lane == 0) { out2[n * 2] = v0 + sbf[0]; out2[n * 2 + 1] = v1 + sbf[1]; }
}

__global__ void __launch_bounds__(256) k_final(const float* __restrict__ W1,
                                               const float* __restrict__ b1,
                                               const float* __restrict__ Wf,
                                               const float* __restrict__ bf,
                                               float* __restrict__ out) {
    __shared__ float sW[4096];
    __shared__ float sb[32], sWf[32];
    int tid = threadIdx.x;
    for (int idx = tid; idx < 4096; idx += 256) sW[idx] = W1[idx];
    if (tid < 32) { sb[tid] = b1[tid]; sWf[tid] = Wf[tid]; }
    __syncthreads();
    int w = tid >> 5, lane = tid & 31;
    int n = blockIdx.x * 8 + w;
    if (n >= NN) return;
    const float* hr = g_agg + n * HH;
    float acc = sb[lane];
    #pragma unroll 8
    for (int k = 0; k < 128; k++) acc += hr[k] * sW[k * 32 + lane];
    float v = fmaxf(acc, 0.f) * sWf[lane];
    #pragma unroll
    for (int off = 16; off > 0; off >>= 1) v += __shfl_xor_sync(0xffffffffu, v, off);
    if (lane == 0) out[n] = 1.f / (1.f + expf(-(v + bf[0])));
}

extern "C" void kernel_launch(void* const* d_in, const int* in_sizes, int n_in,
                              void* d_out, int out_size) {
    const int* z = (const int*)d_in[0];
    const float* pos = (const float*)d_in[1];
    const float* posn = (const float*)d_in[2];
    const float* posc = (const float*)d_in[3];
    const float* bb = (const float*)d_in[4];
    const float* sc = (const float*)d_in[5];
    const float* esm = (const float*)d_in[6];
    const int* ei = (const int*)d_in[8];
    const float* W_emb = (const float*)d_in[9];
    const float* b_emb = (const float*)d_in[10];
    const float* W_esm = (const float*)d_in[11];
    const float* b_esm = (const float*)d_in[12];
    const float* W_edge = (const float*)d_in[13];
    const float* W_msg = (const float*)d_in[14];
    const float* W_upd = (const float*)d_in[15];
    const float* W_o0 = (const float*)d_in[16];
    const float* b_o0 = (const float*)d_in[17];
    const float* W_o1 = (const float*)d_in[18];
    const float* b_o1 = (const float*)d_in[19];
    const float* W_of = (const float*)d_in[20];
    const float* b_of = (const float*)d_in[21];
    const float* W_n0 = (const float*)d_in[22];
    const float* b_n0 = (const float*)d_in[23];
    const float* W_nf = (const float*)d_in[24];
    const float* b_nf = (const float*)d_in[25];
    float* out = (float*)d_out;

    const int GEMM_SMEM = 4 * 128 * 136 * 2;                     // 139264
    const int NEAR_SMEM = 4 * 128 * 136 * 2 + 2 * 128 * 4 + 32;  // 140320
    static cudaStream_t s1 = nullptr, s2 = nullptr;
    static cudaEvent_t evA, evB, evC, evE, evG, evF;
    if (!s1) {
        cudaStreamCreateWithFlags(&s1, cudaStreamNonBlocking);
        cudaStreamCreateWithFlags(&s2, cudaStreamNonBlocking);
        cudaEventCreateWithFlags(&evA, cudaEventDisableTiming);
        cudaEventCreateWithFlags(&evB, cudaEventDisableTiming);
        cudaEventCreateWithFlags(&evC, cudaEventDisableTiming);
        cudaEventCreateWithFlags(&evE, cudaEventDisableTiming);
        cudaEventCreateWithFlags(&evG, cudaEventDisableTiming);
        cudaEventCreateWithFlags(&evF, cudaEventDisableTiming);
        cudaFuncSetAttribute(k_gemm128_tc<0>, cudaFuncAttributeMaxDynamicSharedMemorySize, GEMM_SMEM);
        cudaFuncSetAttribute(k_gemm128_tc<1>, cudaFuncAttributeMaxDynamicSharedMemorySize, GEMM_SMEM);
        cudaFuncSetAttribute(k_gemm128_tc<2>, cudaFuncAttributeMaxDynamicSharedMemorySize, GEMM_SMEM);
        cudaFuncSetAttribute(k_edge_near_tc, cudaFuncAttributeMaxDynamicSharedMemorySize, NEAR_SMEM);
    }

    // fork: esm on s1 overlaps the prologue
    cudaEventRecord(evA, 0);
    cudaStreamWaitEvent(s1, evA, 0);
    k_esm_tc<<<391, 256, 0, s1>>>(esm, W_esm, b_esm);
    cudaEventRecord(evC, s1);                         // esm done

    k_zero<<<6250, 256>>>();
    k_splitW<<<528, 128>>>(W_edge, W_msg, W_upd, W_o0);
    k_classify<<<3907, 256>>>(ei, pos);
    k_embed<<<1563, 256>>>(z, bb, sc, W_emb, b_emb);
    cudaEventRecord(evB, 0);                          // prologue done

    // nodehead needs x (embed + esm); overlaps gemm0/edges
    cudaStreamWaitEvent(s1, evB, 0);
    k_nodehead<<<6250, 256, 0, s1>>>(W_n0, b_n0, W_nf, b_nf, out + NN);
    cudaEventRecord(evE, s1);

    cudaStreamWaitEvent(0, evC, 0);                   // gemm0 needs esm's half of x
    k_gemm128_tc<0><<<391, 256, GEMM_SMEM>>>(nullptr);
    cudaEventRecord(evG, 0);                          // xm ready

    // far on s2 concurrent with near on stream 0
    cudaStreamWaitEvent(s2, evG, 0);
    k_edge_far_tc<<<296, 256, 0, s2>>>();
    cudaEventRecord(evF, s2);

    k_edge_near_tc<<<148, 256, NEAR_SMEM>>>(pos, posn, posc);
    cudaStreamWaitEvent(0, evF, 0);                   // join far before gemm1
    k_gemm128_tc<1><<<391, 256, GEMM_SMEM>>>(nullptr);
    k_gemm128_tc<2><<<391, 256, GEMM_SMEM>>>(b_o0);
    k_final<<<6250, 256>>>(W_o1, b_o1, W_of, b_of, out);
    cudaStreamWaitEvent(0, evE, 0);                   // join nodehead
}

// round 15
// speedup vs baseline: 1.0117x; 1.0117x over previous
#include <cuda_runtime.h>
#include <cuda_bf16.h>
#include <math.h>

#define NN 50000
#define NE 1000000
#define HH 128

__device__ float g_x[NN * HH];
__device__ float g_xm[NN * HH];
__device__ float g_agg[NN * HH];
__device__ int g_ncnt, g_fcnt;
__device__ int2 g_nJI[NE];
__device__ int2 g_fJI[NE];
// pre-split weights (bf16 hi/lo, pitch 136)
__device__ __nv_bfloat16 g_WeH[128 * 136], g_WeL[128 * 136];
__device__ __nv_bfloat16 g_WfH[16 * 136],  g_WfL[16 * 136];
__device__ __nv_bfloat16 g_WmH[128 * 136], g_WmL[128 * 136];
__device__ __nv_bfloat16 g_WuH[128 * 136], g_WuL[128 * 136];
__device__ __nv_bfloat16 g_WoH[128 * 136], g_WoL[128 * 136];

__device__ __forceinline__ float swishf(float v) { return v / (1.f + expf(-v)); }

struct F3 { float x, y, z; };
__device__ __forceinline__ F3 mk3(float a, float b, float c) { F3 r; r.x=a; r.y=b; r.z=c; return r; }
__device__ __forceinline__ F3 sub3(F3 a, F3 b) { return mk3(a.x-b.x, a.y-b.y, a.z-b.z); }
__device__ __forceinline__ F3 crs3(F3 a, F3 b) {
    return mk3(a.y*b.z - a.z*b.y, a.z*b.x - a.x*b.z, a.x*b.y - a.y*b.x);
}
__device__ __forceinline__ float dot3(F3 a, F3 b) { return a.x*b.x + a.y*b.y + a.z*b.z; }
__device__ __forceinline__ F3 ld3(const float* __restrict__ p, int i) {
    return mk3(p[3*i], p[3*i+1], p[3*i+2]);
}
__device__ __forceinline__ unsigned sptr(const void* p) {
    return (unsigned)__cvta_generic_to_shared(p);
}
__device__ __forceinline__ void split2(float x0, float x1, __nv_bfloat162& h, __nv_bfloat162& l) {
    __nv_bfloat16 h0 = __float2bfloat16_rn(x0);
    __nv_bfloat16 h1 = __float2bfloat16_rn(x1);
    h = __halves2bfloat162(h0, h1);
    l = __halves2bfloat162(__float2bfloat16_rn(x0 - __bfloat162float(h0)),
                           __float2bfloat16_rn(x1 - __bfloat162float(h1)));
}
__device__ __forceinline__ void split1(float x, __nv_bfloat16* pH, __nv_bfloat16* pL) {
    __nv_bfloat16 h = __float2bfloat16_rn(x);
    *pH = h;
    *pL = __float2bfloat16_rn(x - __bfloat162float(h));
}
// radial basis via Chebyshev recurrence
__device__ __forceinline__ void radial6(float u, float dist, float* r) {
    float s1, c1;
    sincosf(3.14159274f * u, &s1, &c1);
    float fc = 0.5f * (c1 + 1.f);
    float rs = (float)0.41702882811414954 * fc / (dist + 1e-6f);
    float two_c = 2.f * c1;
    float sm = 0.f, sn = s1;
    r[0] = rs * sn;
    #pragma unroll
    for (int n = 1; n < 6; n++) {
        float sx = two_c * sn - sm;
        sm = sn; sn = sx;
        r[n] = rs * sx;
    }
}

#define LDSM4(r0,r1,r2,r3,addr) \
    asm volatile("ldmatrix.sync.aligned.m8n8.x4.shared.b16 {%0,%1,%2,%3},[%4];" \
                 : "=r"(r0),"=r"(r1),"=r"(r2),"=r"(r3) : "r"(addr))
#define LDSM4T(r0,r1,r2,r3,addr) \
    asm volatile("ldmatrix.sync.aligned.m8n8.x4.trans.shared.b16 {%0,%1,%2,%3},[%4];" \
                 : "=r"(r0),"=r"(r1),"=r"(r2),"=r"(r3) : "r"(addr))
#define MMA16816(d,a0,a1,a2,a3,b0,b1) \
    asm volatile("mma.sync.aligned.m16n8k16.row.col.f32.bf16.bf16.f32 " \
                 "{%0,%1,%2,%3},{%4,%5,%6,%7},{%8,%9},{%0,%1,%2,%3};" \
                 : "+f"(d[0]),"+f"(d[1]),"+f"(d[2]),"+f"(d[3]) \
                 : "r"(a0),"r"(a1),"r"(a2),"r"(a3),"r"(b0),"r"(b1))

__global__ void k_zero() {
    int i = blockIdx.x * 256 + threadIdx.x;
    ((float4*)g_agg)[i] = make_float4(0.f, 0.f, 0.f, 0.f);
    if (i == 0) { g_ncnt = 0; g_fcnt = 0; }
}

__global__ void k_splitW(const float* __restrict__ We, const float* __restrict__ Wm,
                         const float* __restrict__ Wu, const float* __restrict__ Wo) {
    int b = blockIdx.x, tid = threadIdx.x;
    if (b < 128) {
        float v = (b < 124) ? We[b * 128 + tid] : 0.f;
        split1(v, g_WeH + b * 136 + tid, g_WeL + b * 136 + tid);
    } else if (b < 256) {
        int r = b - 128;
        split1(Wm[r * 128 + tid], g_WmH + r * 136 + tid, g_WmL + r * 136 + tid);
    } else if (b < 384) {
        int r = b - 256;
        split1(Wu[r * 128 + tid], g_WuH + r * 136 + tid, g_WuL + r * 136 + tid);
    } else if (b < 512) {
        int r = b - 384;
        split1(Wo[r * 128 + tid], g_WoH + r * 136 + tid, g_WoL + r * 136 + tid);
    } else {
        int r = b - 512;
        split1(We[(108 + r) * 128 + tid], g_WfH + r * 136 + tid, g_WfL + r * 136 + tid);
    }
}

__global__ void k_classify(const int* __restrict__ ei, const float* __restrict__ pos) {
    int e = blockIdx.x * 256 + threadIdx.x;
    bool valid = e < NE;
    int ee = valid ? e : NE - 1;
    int j = ei[ee], i = ei[NE + ee];
    F3 d = sub3(ld3(pos, j), ld3(pos, i));
    float dist = sqrtf(dot3(d, d));
    bool far_ = valid && ((dist / 11.5f) >= 1.f);
    bool near_ = valid && !far_;
    int lane = threadIdx.x & 31;
    unsigned bf = __ballot_sync(0xffffffffu, far_);
    unsigned bn = __ballot_sync(0xffffffffu, near_);
    if (bf) {
        int src = __ffs(bf) - 1;
        int base = 0;
        if (lane == src) base = atomicAdd(&g_fcnt, __popc(bf));
        base = __shfl_sync(0xffffffffu, base, src);
        if (far_) g_fJI[base + __popc(bf & ((1u << lane) - 1))] = make_int2(j, i);
    }
    if (bn) {
        int src = __ffs(bn) - 1;
        int base = 0;
        if (lane == src) base = atomicAdd(&g_ncnt, __popc(bn));
        base = __shfl_sync(0xffffffffu, base, src);
        if (near_) g_nJI[base + __popc(bn & ((1u << lane) - 1))] = make_int2(j, i);
    }
}

__global__ void __launch_bounds__(256) k_embed(const int* __restrict__ z,
                                               const float* __restrict__ bb,
                                               const float* __restrict__ sc,
                                               const float* __restrict__ W,
                                               const float* __restrict__ b) {
    __shared__ float sW[40 * 64];
    __shared__ float sb[64];
    int tid = threadIdx.x;
    for (int idx = tid; idx < 40 * 64; idx += 256) sW[idx] = W[idx];
    if (tid < 64) sb[tid] = b[tid];
    __syncthreads();
    int node = blockIdx.x * 32 + (tid >> 3);
    int c0 = (tid & 7) * 8;
    if (node < NN) {
        float acc[8];
        int zz = z[node];
        #pragma unroll
        for (int cc = 0; cc < 8; cc++) acc[cc] = sb[c0 + cc] + sW[zz * 64 + c0 + cc];
        #pragma unroll
        for (int q = 0; q < 6; q++) {
            float v = bb[node * 6 + q];
            #pragma unroll
            for (int cc = 0; cc < 8; cc++) acc[cc] += v * sW[(26 + q) * 64 + c0 + cc];
        }
        #pragma unroll
        for (int q = 0; q < 8; q++) {
            float v = sc[node * 8 + q];
            #pragma unroll
            for (int cc = 0; cc < 8; cc++) acc[cc] += v * sW[(32 + q) * 64 + c0 + cc];
        }
        float* o = g_x + node * HH + c0;
        *(float4*)o = make_float4(acc[0], acc[1], acc[2], acc[3]);
        *(float4*)(o + 4) = make_float4(acc[4], acc[5], acc[6], acc[7]);
    }
}

__global__ void __launch_bounds__(256) k_esm_tc(const float* __restrict__ esm,
                                                const float* __restrict__ W,
                                                const float* __restrict__ b) {
    __shared__ __nv_bfloat16 AsH[128 * 40];
    __shared__ __nv_bfloat16 AsL[128 * 40];
    __shared__ __nv_bfloat16 BsH[32 * 72];
    __shared__ __nv_bfloat16 BsL[32 * 72];
    int tid = threadIdx.x;
    int m0 = blockIdx.x * 128;
    int wid = tid >> 5, lane = tid & 31;
    int warp_m = wid & 3, warp_n = wid >> 2;
    int arow = tid >> 1, ahalf = tid & 1;
    int grow = m0 + arow; if (grow >= NN) grow = NN - 1;
    const float* aptr = esm + (size_t)grow * 1280 + ahalf * 16;
    int brow = tid >> 3, bcol = (tid & 7) * 8;
    const float* bptr = W + brow * 64 + bcol;
    float acc[2][4][4];
    #pragma unroll
    for (int a_ = 0; a_ < 2; a_++)
        #pragma unroll
        for (int b_ = 0; b_ < 4; b_++)
            #pragma unroll
            for (int q = 0; q < 4; q++) acc[a_][b_][q] = 0.f;
    float4 ra[4]; float4 rb[2];
    #pragma unroll
    for (int q = 0; q < 4; q++) ra[q] = *(const float4*)(aptr + q * 4);
    rb[0] = *(const float4*)bptr; rb[1] = *(const float4*)(bptr + 4);
    int a_r = lane & 15, a_c = (lane >> 4) * 8;
    int b_k = lane & 15, b_n = (lane >> 4) * 8;
    for (int c = 0; c < 40; c++) {
        {
            float av[16] = {ra[0].x, ra[0].y, ra[0].z, ra[0].w,
                            ra[1].x, ra[1].y, ra[1].z, ra[1].w,
                            ra[2].x, ra[2].y, ra[2].z, ra[2].w,
                            ra[3].x, ra[3].y, ra[3].z, ra[3].w};
            __nv_bfloat162* dH = (__nv_bfloat162*)(AsH + arow * 40 + ahalf * 16);
            __nv_bfloat162* dL = (__nv_bfloat162*)(AsL + arow * 40 + ahalf * 16);
            #pragma unroll
            for (int q = 0; q < 8; q++) {
                __nv_bfloat162 h, l;
                split2(av[2 * q], av[2 * q + 1], h, l);
                dH[q] = h; dL[q] = l;
            }
            float bv[8] = {rb[0].x, rb[0].y, rb[0].z, rb[0].w,
                           rb[1].x, rb[1].y, rb[1].z, rb[1].w};
            __nv_bfloat162* eH = (__nv_bfloat162*)(BsH + brow * 72 + bcol);
            __nv_bfloat162* eL = (__nv_bfloat162*)(BsL + brow * 72 + bcol);
            #pragma unroll
            for (int q = 0; q < 4; q++) {
                __nv_bfloat162 h, l;
                split2(bv[2 * q], bv[2 * q + 1], h, l);
                eH[q] = h; eL[q] = l;
            }
        }
        __syncthreads();
        if (c < 39) {
            aptr += 32; bptr += 32 * 64;
            #pragma unroll
            for (int q = 0; q < 4; q++) ra[q] = *(const float4*)(aptr + q * 4);
            rb[0] = *(const float4*)bptr; rb[1] = *(const float4*)(bptr + 4);
        }
        #pragma unroll
        for (int ks = 0; ks < 2; ks++) {
            unsigned ah[2][4], al[2][4], bh[2][4], bl[2][4];
            #pragma unroll
            for (int mt = 0; mt < 2; mt++) {
                int row = warp_m * 32 + mt * 16 + a_r;
                int col = ks * 16 + a_c;
                LDSM4(ah[mt][0], ah[mt][1], ah[mt][2], ah[mt][3], sptr(AsH + row * 40 + col));
                LDSM4(al[mt][0], al[mt][1], al[mt][2], al[mt][3], sptr(AsL + row * 40 + col));
            }
            #pragma unroll
            for (int g = 0; g < 2; g++) {
                int kk = ks * 16 + b_k;
                int nn = warp_n * 32 + g * 16 + b_n;
                LDSM4T(bh[g][0], bh[g][1], bh[g][2], bh[g][3], sptr(BsH + kk * 72 + nn));
                LDSM4T(bl[g][0], bl[g][1], bl[g][2], bl[g][3], sptr(BsL + kk * 72 + nn));
            }
            #pragma unroll
            for (int mt = 0; mt < 2; mt++)
                #pragma unroll
                for (int nt = 0; nt < 4; nt++) {
                    int g = nt >> 1, h = (nt & 1) * 2;
                    MMA16816(acc[mt][nt], ah[mt][0], ah[mt][1], ah[mt][2], ah[mt][3],
                             bh[g][h], bh[g][h + 1]);
                    MMA16816(acc[mt][nt], ah[mt][0], ah[mt][1], ah[mt][2], ah[mt][3],
                             bl[g][h], bl[g][h + 1]);
                    MMA16816(acc[mt][nt], al[mt][0], al[mt][1], al[mt][2], al[mt][3],
                             bh[g][h], bh[g][h + 1]);
                }
        }
        __syncthreads();
    }
    #pragma unroll
    for (int mt = 0; mt < 2; mt++)
        #pragma unroll
        for (int nt = 0; nt < 4; nt++) {
            int row = m0 + warp_m * 32 + mt * 16 + (lane >> 2);
            int col = warp_n * 32 + nt * 8 + (lane & 3) * 2;
            if (row < NN) {
                g_x[row * HH + 64 + col] = acc[mt][nt][0] + b[col];
                g_x[row * HH + 64 + col + 1] = acc[mt][nt][1] + b[col + 1];
            }
            if (row + 8 < NN) {
                g_x[(row + 8) * HH + 64 + col] = acc[mt][nt][2] + b[col];
                g_x[(row + 8) * HH + 64 + col + 1] = acc[mt][nt][3] + b[col + 1];
            }
        }
}

// core mma over staged A/B (shared by gemm kernels)
__device__ __forceinline__ void mma128(const __nv_bfloat16* AsH, const __nv_bfloat16* AsL,
                                       const __nv_bfloat16* BsH, const __nv_bfloat16* BsL,
                                       float acc[2][8][4], int warp_m, int warp_n, int lane) {
    int a_r = lane & 15, a_c = (lane >> 4) * 8;
    int b_k = lane & 15, b_n = (lane >> 4) * 8;
    #pragma unroll
    for (int ks = 0; ks < 8; ks++) {
        unsigned ah[2][4], al[2][4];
        #pragma unroll
        for (int mt = 0; mt < 2; mt++) {
            int row = warp_m * 32 + mt * 16 + a_r;
            int col = ks * 16 + a_c;
            LDSM4(ah[mt][0], ah[mt][1], ah[mt][2], ah[mt][3], sptr(AsH + row * 136 + col));
            LDSM4(al[mt][0], al[mt][1], al[mt][2], al[mt][3], sptr(AsL + row * 136 + col));
        }
        #pragma unroll
        for (int g = 0; g < 4; g++) {
            unsigned bh[4], bl[4];
            int kk = ks * 16 + b_k;
            int nn = warp_n * 64 + g * 16 + b_n;
            LDSM4T(bh[0], bh[1], bh[2], bh[3], sptr(BsH + kk * 136 + nn));
            LDSM4T(bl[0], bl[1], bl[2], bl[3], sptr(BsL + kk * 136 + nn));
            #pragma unroll
            for (int mt = 0; mt < 2; mt++)
                #pragma unroll
                for (int t8 = 0; t8 < 2; t8++) {
                    int h = t8 * 2;
                    float* d = acc[mt][g * 2 + t8];
                    MMA16816(d, ah[mt][0], ah[mt][1], ah[mt][2], ah[mt][3], bh[h], bh[h + 1]);
                    MMA16816(d, ah[mt][0], ah[mt][1], ah[mt][2], ah[mt][3], bl[h], bl[h + 1]);
                    MMA16816(d, al[mt][0], al[mt][1], al[mt][2], al[mt][3], bh[h], bh[h + 1]);
                }
        }
    }
}

// gemm0: xm = swish(x @ W_msg)
__global__ void __launch_bounds__(256) k_gemm0_tc() {
    extern __shared__ __align__(16) char smraw[];
    __nv_bfloat16* AsH = (__nv_bfloat16*)smraw;
    __nv_bfloat16* AsL = AsH + 128 * 136;
    __nv_bfloat16* BsH = AsL + 128 * 136;
    __nv_bfloat16* BsL = BsH + 128 * 136;
    int tid = threadIdx.x;
    int m0 = blockIdx.x * 128;
    int wid = tid >> 5, lane = tid & 31;
    int warp_m = wid & 3, warp_n = wid >> 2;
    {
        const uint4* sH = (const uint4*)g_WmH;
        const uint4* sL = (const uint4*)g_WmL;
        uint4* dH = (uint4*)BsH;
        uint4* dL = (uint4*)BsL;
        for (int idx = tid; idx < 2176; idx += 256) { dH[idx] = sH[idx]; dL[idx] = sL[idx]; }
    }
    {
        int row = tid >> 1, half = tid & 1;
        int grow = m0 + row; if (grow >= NN) grow = NN - 1;
        const float* ap = g_x + grow * HH + half * 64;
        __nv_bfloat162* dH = (__nv_bfloat162*)(AsH + row * 136 + half * 64);
        __nv_bfloat162* dL = (__nv_bfloat162*)(AsL + row * 136 + half * 64);
        #pragma unroll
        for (int q = 0; q < 16; q++) {
            float4 v = ((const float4*)ap)[q];
            __nv_bfloat162 h, l;
            split2(v.x, v.y, h, l); dH[2 * q] = h; dL[2 * q] = l;
            split2(v.z, v.w, h, l); dH[2 * q + 1] = h; dL[2 * q + 1] = l;
        }
    }
    __syncthreads();
    float acc[2][8][4];
    #pragma unroll
    for (int a_ = 0; a_ < 2; a_++)
        #pragma unroll
        for (int b_ = 0; b_ < 8; b_++)
            #pragma unroll
            for (int q = 0; q < 4; q++) acc[a_][b_][q] = 0.f;
    mma128(AsH, AsL, BsH, BsL, acc, warp_m, warp_n, lane);
    #pragma unroll
    for (int mt = 0; mt < 2; mt++)
        #pragma unroll
        for (int nt = 0; nt < 8; nt++) {
            int row = m0 + warp_m * 32 + mt * 16 + (lane >> 2);
            int col = warp_n * 64 + nt * 8 + (lane & 3) * 2;
            float* d = acc[mt][nt];
            #pragma unroll
            for (int rr = 0; rr < 2; rr++) {
                int r = row + rr * 8;
                if (r < NN)
                    *(float2*)(g_xm + r * HH + col) =
                        make_float2(swishf(d[rr * 2]), swishf(d[rr * 2 + 1]));
            }
        }
}

// fused gemm1+gemm2: xe = x + swish(agg@W_upd); h0 = relu(xe@W_o0 + b) -> g_agg
__global__ void __launch_bounds__(256) k_gemm12_tc(const float* __restrict__ bias) {
    extern __shared__ __align__(16) char smraw[];
    __nv_bfloat16* AsH = (__nv_bfloat16*)smraw;
    __nv_bfloat16* AsL = AsH + 128 * 136;
    __nv_bfloat16* BsH = AsL + 128 * 136;
    __nv_bfloat16* BsL = BsH + 128 * 136;
    int tid = threadIdx.x;
    int m0 = blockIdx.x * 128;
    int wid = tid >> 5, lane = tid & 31;
    int warp_m = wid & 3, warp_n = wid >> 2;
    // stage W_upd + A=g_agg
    {
        const uint4* sH = (const uint4*)g_WuH;
        const uint4* sL = (const uint4*)g_WuL;
        uint4* dH = (uint4*)BsH;
        uint4* dL = (uint4*)BsL;
        for (int idx = tid; idx < 2176; idx += 256) { dH[idx] = sH[idx]; dL[idx] = sL[idx]; }
    }
    {
        int row = tid >> 1, half = tid & 1;
        int grow = m0 + row; if (grow >= NN) grow = NN - 1;
        const float* ap = g_agg + grow * HH + half * 64;
        __nv_bfloat162* dH = (__nv_bfloat162*)(AsH + row * 136 + half * 64);
        __nv_bfloat162* dL = (__nv_bfloat162*)(AsL + row * 136 + half * 64);
        #pragma unroll
        for (int q = 0; q < 16; q++) {
            float4 v = ((const float4*)ap)[q];
            __nv_bfloat162 h, l;
            split2(v.x, v.y, h, l); dH[2 * q] = h; dL[2 * q] = l;
            split2(v.z, v.w, h, l); dH[2 * q + 1] = h; dL[2 * q + 1] = l;
        }
    }
    __syncthreads();
    float acc[2][8][4];
    #pragma unroll
    for (int a_ = 0; a_ < 2; a_++)
        #pragma unroll
        for (int b_ = 0; b_ < 8; b_++)
            #pragma unroll
            for (int q = 0; q < 4; q++) acc[a_][b_][q] = 0.f;
    mma128(AsH, AsL, BsH, BsL, acc, warp_m, warp_n, lane);
    __syncthreads();   // all LDSM reads of As/Bs complete before overwrite
    // epilogue1: xe = x + swish(acc); write split xe into As; stage W_o0 into Bs
    #pragma unroll
    for (int mt = 0; mt < 2; mt++)
        #pragma unroll
        for (int nt = 0; nt < 8; nt++) {
            int rloc = warp_m * 32 + mt * 16 + (lane >> 2);
            int col = warp_n * 64 + nt * 8 + (lane & 3) * 2;
            float* d = acc[mt][nt];
            #pragma unroll
            for (int rr = 0; rr < 2; rr++) {
                int rl = rloc + rr * 8;
                int gr = m0 + rl; if (gr >= NN) gr = NN - 1;
                float2 xv = *(const float2*)(g_x + gr * HH + col);
                float e0 = xv.x + swishf(d[rr * 2]);
                float e1 = xv.y + swishf(d[rr * 2 + 1]);
                __nv_bfloat162 h, l;
                split2(e0, e1, h, l);
                *(__nv_bfloat162*)(AsH + rl * 136 + col) = h;
                *(__nv_bfloat162*)(AsL + rl * 136 + col) = l;
            }
        }
    {
        const uint4* sH = (const uint4*)g_WoH;
        const uint4* sL = (const uint4*)g_WoL;
        uint4* dH = (uint4*)BsH;
        uint4* dL = (uint4*)BsL;
        for (int idx = tid; idx < 2176; idx += 256) { dH[idx] = sH[idx]; dL[idx] = sL[idx]; }
    }
    __syncthreads();
    #pragma unroll
    for (int a_ = 0; a_ < 2; a_++)
        #pragma unroll
        for (int b_ = 0; b_ < 8; b_++)
            #pragma unroll
            for (int q = 0; q < 4; q++) acc[a_][b_][q] = 0.f;
    mma128(AsH, AsL, BsH, BsL, acc, warp_m, warp_n, lane);
    // epilogue2: h0 = relu(acc + bias) -> g_agg
    #pragma unroll
    for (int mt = 0; mt < 2; mt++)
        #pragma unroll
        for (int nt = 0; nt < 8; nt++) {
            int row = m0 + warp_m * 32 + mt * 16 + (lane >> 2);
            int col = warp_n * 64 + nt * 8 + (lane & 3) * 2;
            float* d = acc[mt][nt];
            #pragma unroll
            for (int rr = 0; rr < 2; rr++) {
                int r = row + rr * 8;
                if (r < NN)
                    *(float2*)(g_agg + r * HH + col) =
                        make_float2(fmaxf(d[rr * 2] + bias[col], 0.f),
                                    fmaxf(d[rr * 2 + 1] + bias[col + 1], 0.f));
            }
        }
}

__device__ __forceinline__ void edge_scatter(float acc[2][8][4], const int* js, const int* is_,
                                             int warp_m, int warp_n, int lane) {
    #pragma unroll
    for (int mt = 0; mt < 2; mt++)
        #pragma unroll
        for (int nt = 0; nt < 8; nt++) {
            int el = warp_m * 32 + mt * 16 + (lane >> 2);
            int col = warp_n * 64 + nt * 8 + (lane & 3) * 2;
            float* d = acc[mt][nt];
            #pragma unroll
            for (int rr = 0; rr < 2; rr++) {
                int e = el + rr * 8;
                int j = js[e];
                if (j >= 0) {
                    int i = is_[e];
                    float2 xv = *(const float2*)(g_xm + j * HH + col);
                    float m0 = swishf(d[rr * 2]) * xv.x;
                    float m1 = swishf(d[rr * 2 + 1]) * xv.y;
                    asm volatile("red.global.add.v2.f32 [%0], {%1,%2};"
                                 :: "l"(g_agg + i * HH + col), "f"(m0), "f"(m1) : "memory");
                }
            }
        }
}

// near edges: persistent blocks, W staged once, geometry split across 2 threads/edge
__global__ void __launch_bounds__(256) k_edge_near_tc(const float* __restrict__ pos,
                                                      const float* __restrict__ posn,
                                                      const float* __restrict__ posc) {
    int cnt = g_ncnt;
    extern __shared__ __align__(16) char smraw[];
    __nv_bfloat16* WsH = (__nv_bfloat16*)smraw;
    __nv_bfloat16* WsL = WsH + 128 * 136;
    __nv_bfloat16* FsH = WsL + 128 * 136;
    __nv_bfloat16* FsL = FsH + 128 * 136;
    int* js = (int*)(FsL + 128 * 136);
    int* is_ = js + 128;
    float* freqs = (float*)(is_ + 128);
    int tid = threadIdx.x;
    int wid = tid >> 5, lane = tid & 31;
    int warp_m = wid & 3, warp_n = wid >> 2;
    int e = tid & 127, role = tid >> 7;

    {
        const uint4* sH = (const uint4*)g_WeH;
        const uint4* sL = (const uint4*)g_WeL;
        uint4* dH = (uint4*)WsH;
        uint4* dL = (uint4*)WsL;
        for (int idx = tid; idx < 2176; idx += 256) { dH[idx] = sH[idx]; dL[idx] = sL[idx]; }
    }
    if (tid < 8) {
        float t = (float)(2 * tid) * (float)(-0.5756462732485115);
        freqs[tid] = (float)exp((double)t);
    }

    for (int t0 = blockIdx.x * 128; t0 < cnt; t0 += gridDim.x * 128) {
        __syncthreads();
        {
            int idx = t0 + e;
            bool valid = idx < cnt;
            int2 ji = g_nJI[valid ? idx : cnt - 1];
            int j = ji.x, i = ji.y;
            if (role == 0) { js[e] = valid ? j : -1; is_[e] = i; }
            __nv_bfloat16* fH = FsH + e * 136;
            __nv_bfloat16* fL = FsL + e * 136;
            F3 pi_ = ld3(pos, i), pj = ld3(pos, j);
            F3 vji = sub3(pj, pi_);
            float dist = sqrtf(dot3(vji, vji));
            float u = fminf(dist / 11.5f, 1.f);
            float r[6];
            radial6(u, dist, r);
            if (role == 0) {
                int r0 = (i == 0) ? NN - 1 : i - 1;
                int r1 = (i == NN - 1) ? 0 : i + 1;
                F3 vr0 = sub3(ld3(pos, r0), pi_);
                F3 vr1 = sub3(ld3(pos, r1), pi_);
                float a = dot3(vji, vr0);
                F3 cr = crs3(vji, vr0);
                float b2 = dot3(cr, cr);
                float ct1 = a * rsqrtf(fmaxf(a * a + b2, 1e-30f));
                float ct2 = 2.f * ct1 * ct1 - 1.f;
                F3 p1 = crs3(vr0, vr1), p2 = crs3(vr0, vji);
                float ap = dot3(p1, p2);
                F3 c12 = crs3(p1, p2);
                float bp = dot3(c12, vr0) / (sqrtf(dot3(vr0, vr0)) + 1e-7f);
                float cp1 = ap * rsqrtf(fmaxf(ap * ap + bp * bp, 1e-30f));
                float cp2 = 2.f * cp1 * cp1 - 1.f;
                float ct[3] = {1.f, ct1, ct2};
                float cp[3] = {1.f, cp1, cp2};
                #pragma unroll
                for (int n = 0; n < 6; n++)
                    #pragma unroll
                    for (int l = 0; l < 3; l++) {
                        float rl = r[n] * ct[l];
                        #pragma unroll
                        for (int m = 0; m < 3; m++) {
                            int k = n * 9 + l * 3 + m;
                            split1(rl * cp[m], fH + k, fL + k);
                        }
                    }
                float dpe = (float)(j - i);
                #pragma unroll
                for (int kk = 0; kk < 8; kk++) {
                    float s, c;
                    sincosf(dpe * freqs[kk], &s, &c);
                    split1(c, fH + 108 + kk, fL + 108 + kk);
                    split1(s, fH + 116 + kk, fL + 116 + kk);
                }
            } else {
                F3 o1x = sub3(ld3(posn, i), pi_);
                F3 o1z = crs3(o1x, crs3(o1x, sub3(ld3(posc, i), pi_)));
                float o1zl = sqrtf(dot3(o1z, o1z)) + 1e-7f;
                F3 o2x = sub3(ld3(posn, j), pj);
                F3 o2z = crs3(o2x, crs3(o2x, sub3(ld3(posc, j), pj)));
                float o2zl = sqrtf(dot3(o2z, o2z)) + 1e-7f;
                F3 nv = crs3(o1z, o2z);
                float a1 = dot3(o1x, nv);
                float b1 = dot3(crs3(o1x, nv), o1z) / o1zl;
                float cA10 = a1 * rsqrtf(fmaxf(a1 * a1 + b1 * b1, 1e-30f));
                float cA11 = 2.f * cA10 * cA10 - 1.f;
                float a2 = dot3(o1z, o2z);
                float b2v = sqrtf(dot3(nv, nv));
                float cA20 = a2 * rsqrtf(fmaxf(a2 * a2 + b2v * b2v, 1e-30f));
                float cA21 = 2.f * cA20 * cA20 - 1.f;
                float a3 = dot3(nv, o2x);
                float b3 = dot3(crs3(nv, o2x), o2z) / o2zl;
                float cA30 = a3 * rsqrtf(fmaxf(a3 * a3 + b3 * b3, 1e-30f));
                float cA31 = 2.f * cA30 * cA30 - 1.f;
                float cA[3][3] = {{1.f, cA10, cA11}, {1.f, cA20, cA21}, {1.f, cA30, cA31}};
                #pragma unroll
                for (int t = 0; t < 3; t++)
                    #pragma unroll
                    for (int n = 0; n < 6; n++)
                        #pragma unroll
                        for (int l = 0; l < 3; l++) {
                            int k = 54 + t * 18 + n * 3 + l;
                            split1(r[n] * cA[t][l], fH + k, fL + k);
                        }
                __nv_bfloat16 zb = __float2bfloat16_rn(0.f);
                #pragma unroll
                for (int k = 124; k < 128; k++) { fH[k] = zb; fL[k] = zb; }
            }
        }
        __syncthreads();

        float acc[2][8][4];
        #pragma unroll
        for (int a_ = 0; a_ < 2; a_++)
            #pragma unroll
            for (int b_ = 0; b_ < 8; b_++)
                #pragma unroll
                for (int q = 0; q < 4; q++) acc[a_][b_][q] = 0.f;
        mma128(FsH, FsL, WsH, WsL, acc, warp_m, warp_n, lane);
        edge_scatter(acc, js, is_, warp_m, warp_n, lane);
    }
}

// far edges: persistent blocks (small smem), PE split across 2 threads/edge
__global__ void __launch_bounds__(256) k_edge_far_tc() {
    int cnt = g_fcnt;
    __shared__ __align__(16) __nv_bfloat16 WsH[16 * 136], WsL[16 * 136];
    __shared__ __align__(16) __nv_bfloat16 FsH[128 * 24], FsL[128 * 24];
    __shared__ int js[128], is_[128];
    __shared__ float freqs[8];
    int tid = threadIdx.x;
    int wid = tid >> 5, lane = tid & 31;
    int warp_m = wid & 3, warp_n = wid >> 2;
    int e = tid & 127, role = tid >> 7;

    {
        const uint4* sH = (const uint4*)g_WfH;
        const uint4* sL = (const uint4*)g_WfL;
        uint4* dH = (uint4*)WsH;
        uint4* dL = (uint4*)WsL;
        for (int idx = tid; idx < 272; idx += 256) { dH[idx] = sH[idx]; dL[idx] = sL[idx]; }
    }
    if (tid < 8) {
        float t = (float)(2 * tid) * (float)(-0.5756462732485115);
        freqs[tid] = (float)exp((double)t);
    }

    int a_r = lane & 15, a_c = (lane >> 4) * 8;
    int b_k = lane & 15, b_n = (lane >> 4) * 8;

    for (int t0 = blockIdx.x * 128; t0 < cnt; t0 += gridDim.x * 128) {
        __syncthreads();
        {
            int idx = t0 + e;
            bool valid = idx < cnt;
            int2 ji = g_fJI[valid ? idx : cnt - 1];
            int j = ji.x, i = ji.y;
            if (role == 0) { js[e] = valid ? j : -1; is_[e] = i; }
            float dpe = (float)(j - i);
            __nv_bfloat16* fH = FsH + e * 24;
            __nv_bfloat16* fL = FsL + e * 24;
            #pragma unroll
            for (int q = 0; q < 4; q++) {
                int kk = role * 4 + q;
                float s, c;
                sincosf(dpe * freqs[kk], &s, &c);
                split1(c, fH + kk, fL + kk);
                split1(s, fH + 8 + kk, fL + 8 + kk);
            }
        }
        __syncthreads();

        float acc[2][8][4];
        #pragma unroll
        for (int a_ = 0; a_ < 2; a_++)
            #pragma unroll
            for (int b_ = 0; b_ < 8; b_++)
                #pragma unroll
                for (int q = 0; q < 4; q++) acc[a_][b_][q] = 0.f;
        unsigned ah[2][4], al[2][4];
        #pragma unroll
        for (int mt = 0; mt < 2; mt++) {
            int row = warp_m * 32 + mt * 16 + a_r;
            LDSM4(ah[mt][0], ah[mt][1], ah[mt][2], ah[mt][3], sptr(FsH + row * 24 + a_c));
            LDSM4(al[mt][0], al[mt][1], al[mt][2], al[mt][3], sptr(FsL + row * 24 + a_c));
        }
        #pragma unroll
        for (int g = 0; g < 4; g++) {
            unsigned bh[4], bl[4];
            int nn = warp_n * 64 + g * 16 + b_n;
            LDSM4T(bh[0], bh[1], bh[2], bh[3], sptr(WsH + b_k * 136 + nn));
            LDSM4T(bl[0], bl[1], bl[2], bl[3], sptr(WsL + b_k * 136 + nn));
            #pragma unroll
            for (int mt = 0; mt < 2; mt++)
                #pragma unroll
                for (int t8 = 0; t8 < 2; t8++) {
                    int h = t8 * 2;
                    float* d = acc[mt][g * 2 + t8];
                    MMA16816(d, ah[mt][0], ah[mt][1], ah[mt][2], ah[mt][3], bh[h], bh[h + 1]);
                    MMA16816(d, ah[mt][0], ah[mt][1], ah[mt][2], ah[mt][3], bl[h], bl[h + 1]);
                    MMA16816(d, al[mt][0], al[mt][1], al[mt][2], al[mt][3], bh[h], bh[h + 1]);
                }
        }
        edge_scatter(acc, js, is_, warp_m, warp_n, lane);
    }
}

__global__ void __launch_bounds__(256) k_nodehead(const float* __restrict__ W0,
                                                  const float* __restrict__ b0,
                                                  const float* __restrict__ Wf,
                                                  const float* __restrict__ bf,
                                                  float* __restrict__ out2) {
    __shared__ float sW[4096];
    __shared__ float sb[32], sWf[64], sbf[2];
    int tid = threadIdx.x;
    for (int idx = tid; idx < 4096; idx += 256) sW[idx] = W0[idx];
    if (tid < 32) sb[tid] = b0[tid];
    if (tid < 64) sWf[tid] = Wf[tid];
    if (tid < 2) sbf[tid] = bf[tid];
    __syncthreads();
    int w = tid >> 5, lane = tid & 31;
    int n = blockIdx.x * 8 + w;
    if (n >= NN) return;
    const float* xr = g_x + n * HH;
    float acc = sb[lane];
    #pragma unroll 8
    for (int k = 0; k < 128; k++) acc += xr[k] * sW[k * 32 + lane];
    float xn = fmaxf(acc, 0.f);
    float v0 = xn * sWf[lane * 2], v1 = xn * sWf[lane * 2 + 1];
    #pragma unroll
    for (int off = 16; off > 0; off >>= 1) {
        v0 += __shfl_xor_sync(0xffffffffu, v0, off);
        v1 += __shfl_xor_sync(0xffffffffu, v1, off);
    }
    if (lane == 0) { out2[n * 2] = v0 + sbf[0]; out2[n * 2 + 1] = v1 + sbf[1]; }
}

__global__ void __launch_bounds__(256) k_final(const float* __restrict__ W1,
                                               const float* __restrict__ b1,
                                               const float* __restrict__ Wf,
                                               const float* __restrict__ bf,
                                               float* __restrict__ out) {
    __shared__ float sW[4096];
    __shared__ float sb[32], sWf[32];
    int tid = threadIdx.x;
    for (int idx = tid; idx < 4096; idx += 256) sW[idx] = W1[idx];
    if (tid < 32) { sb[tid] = b1[tid]; sWf[tid] = Wf[tid]; }
    __syncthreads();
    int w = tid >> 5, lane = tid & 31;
    int n = blockIdx.x * 8 + w;
    if (n >= NN) return;
    const float* hr = g_agg + n * HH;
    float acc = sb[lane];
    #pragma unroll 8
    for (int k = 0; k < 128; k++) acc += hr[k] * sW[k * 32 + lane];
    float v = fmaxf(acc, 0.f) * sWf[lane];
    #pragma unroll
    for (int off = 16; off > 0; off >>= 1) v += __shfl_xor_sync(0xffffffffu, v, off);
    if (lane == 0) out[n] = 1.f / (1.f + expf(-(v + bf[0])));
}

extern "C" void kernel_launch(void* const* d_in, const int* in_sizes, int n_in,
                              void* d_out, int out_size) {
    const int* z = (const int*)d_in[0];
    const float* pos = (const float*)d_in[1];
    const float* posn = (const float*)d_in[2];
    const float* posc = (const float*)d_in[3];
    const float* bb = (const float*)d_in[4];
    const float* sc = (const float*)d_in[5];
    const float* esm = (const float*)d_in[6];
    const int* ei = (const int*)d_in[8];
    const float* W_emb = (const float*)d_in[9];
    const float* b_emb = (const float*)d_in[10];
    const float* W_esm = (const float*)d_in[11];
    const float* b_esm = (const float*)d_in[12];
    const float* W_edge = (const float*)d_in[13];
    const float* W_msg = (const float*)d_in[14];
    const float* W_upd = (const float*)d_in[15];
    const float* W_o0 = (const float*)d_in[16];
    const float* b_o0 = (const float*)d_in[17];
    const float* W_o1 = (const float*)d_in[18];
    const float* b_o1 = (const float*)d_in[19];
    const float* W_of = (const float*)d_in[20];
    const float* b_of = (const float*)d_in[21];
    const float* W_n0 = (const float*)d_in[22];
    const float* b_n0 = (const float*)d_in[23];
    const float* W_nf = (const float*)d_in[24];
    const float* b_nf = (const float*)d_in[25];
    float* out = (float*)d_out;

    const int GEMM_SMEM = 4 * 128 * 136 * 2;                     // 139264
    const int NEAR_SMEM = 4 * 128 * 136 * 2 + 2 * 128 * 4 + 32;  // 140320
    static cudaStream_t s1 = nullptr, s2 = nullptr;
    static cudaEvent_t evA, evB, evC, evE, evG, evF;
    if (!s1) {
        cudaStreamCreateWithFlags(&s1, cudaStreamNonBlocking);
        cudaStreamCreateWithFlags(&s2, cudaStreamNonBlocking);
        cudaEventCreateWithFlags(&evA, cudaEventDisableTiming);
        cudaEventCreateWithFlags(&evB, cudaEventDisableTiming);
        cudaEventCreateWithFlags(&evC, cudaEventDisableTiming);
        cudaEventCreateWithFlags(&evE, cudaEventDisableTiming);
        cudaEventCreateWithFlags(&evG, cudaEventDisableTiming);
        cudaEventCreateWithFlags(&evF, cudaEventDisableTiming);
        cudaFuncSetAttribute(k_gemm0_tc, cudaFuncAttributeMaxDynamicSharedMemorySize, GEMM_SMEM);
        cudaFuncSetAttribute(k_gemm12_tc, cudaFuncAttributeMaxDynamicSharedMemorySize, GEMM_SMEM);
        cudaFuncSetAttribute(k_edge_near_tc, cudaFuncAttributeMaxDynamicSharedMemorySize, NEAR_SMEM);
    }

    // fork: esm on s1 overlaps the prologue
    cudaEventRecord(evA, 0);
    cudaStreamWaitEvent(s1, evA, 0);
    k_esm_tc<<<391, 256, 0, s1>>>(esm, W_esm, b_esm);
    cudaEventRecord(evC, s1);                         // esm done

    k_zero<<<6250, 256>>>();
    k_splitW<<<528, 128>>>(W_edge, W_msg, W_upd, W_o0);
    k_classify<<<3907, 256>>>(ei, pos);
    k_embed<<<1563, 256>>>(z, bb, sc, W_emb, b_emb);
    cudaEventRecord(evB, 0);                          // prologue done

    // nodehead needs x (embed + esm); overlaps gemm0/edges
    cudaStreamWaitEvent(s1, evB, 0);
    k_nodehead<<<6250, 256, 0, s1>>>(W_n0, b_n0, W_nf, b_nf, out + NN);
    cudaEventRecord(evE, s1);

    cudaStreamWaitEvent(0, evC, 0);                   // gemm0 needs esm's half of x
    k_gemm0_tc<<<391, 256, GEMM_SMEM>>>();
    cudaEventRecord(evG, 0);                          // xm ready

    // far on s2 concurrent with near on stream 0
    cudaStreamWaitEvent(s2, evG, 0);
    k_edge_far_tc<<<296, 256, 0, s2>>>();
    cudaEventRecord(evF, s2);

    k_edge_near_tc<<<148, 256, NEAR_SMEM>>>(pos, posn, posc);
    cudaStreamWaitEvent(0, evF, 0);                   // join far before fused gemm
    k_gemm12_tc<<<391, 256, GEMM_SMEM>>>(b_o0);
    k_final<<<6250, 256>>>(W_o1, b_o1, W_of, b_of, out);
    cudaStreamWaitEvent(0, evE, 0);                   // join nodehead
}

// round 16
// speedup vs baseline: 1.0987x; 1.0860x over previous
#include <cuda_runtime.h>
#include <cuda_bf16.h>
#include <math.h>

#define NN 50000
#define NE 1000000
#define HH 128

__device__ float g_x[NN * HH];
__device__ float g_xm[NN * HH];
__device__ float g_agg[NN * HH];
__device__ int g_ncnt, g_fcnt;
__device__ int2 g_nJI[NE];
__device__ int2 g_fJI[NE];
// pre-split weights (bf16 hi/lo, pitch 136)
__device__ __nv_bfloat16 g_WeH[128 * 136], g_WeL[128 * 136];
__device__ __nv_bfloat16 g_WfH[16 * 136],  g_WfL[16 * 136];
__device__ __nv_bfloat16 g_WmH[128 * 136], g_WmL[128 * 136];
__device__ __nv_bfloat16 g_WuH[128 * 136], g_WuL[128 * 136];
__device__ __nv_bfloat16 g_WoH[128 * 136], g_WoL[128 * 136];

__device__ __forceinline__ float swishf(float v) { return v / (1.f + expf(-v)); }

struct F3 { float x, y, z; };
__device__ __forceinline__ F3 mk3(float a, float b, float c) { F3 r; r.x=a; r.y=b; r.z=c; return r; }
__device__ __forceinline__ F3 sub3(F3 a, F3 b) { return mk3(a.x-b.x, a.y-b.y, a.z-b.z); }
__device__ __forceinline__ F3 crs3(F3 a, F3 b) {
    return mk3(a.y*b.z - a.z*b.y, a.z*b.x - a.x*b.z, a.x*b.y - a.y*b.x);
}
__device__ __forceinline__ float dot3(F3 a, F3 b) { return a.x*b.x + a.y*b.y + a.z*b.z; }
__device__ __forceinline__ F3 ld3(const float* __restrict__ p, int i) {
    return mk3(p[3*i], p[3*i+1], p[3*i+2]);
}
__device__ __forceinline__ unsigned sptr(const void* p) {
    return (unsigned)__cvta_generic_to_shared(p);
}
__device__ __forceinline__ void split2(float x0, float x1, __nv_bfloat162& h, __nv_bfloat162& l) {
    __nv_bfloat16 h0 = __float2bfloat16_rn(x0);
    __nv_bfloat16 h1 = __float2bfloat16_rn(x1);
    h = __halves2bfloat162(h0, h1);
    l = __halves2bfloat162(__float2bfloat16_rn(x0 - __bfloat162float(h0)),
                           __float2bfloat16_rn(x1 - __bfloat162float(h1)));
}
__device__ __forceinline__ void split1(float x, __nv_bfloat16* pH, __nv_bfloat16* pL) {
    __nv_bfloat16 h = __float2bfloat16_rn(x);
    *pH = h;
    *pL = __float2bfloat16_rn(x - __bfloat162float(h));
}
// radial basis via Chebyshev recurrence
__device__ __forceinline__ void radial6(float u, float dist, float* r) {
    float s1, c1;
    sincosf(3.14159274f * u, &s1, &c1);
    float fc = 0.5f * (c1 + 1.f);
    float rs = (float)0.41702882811414954 * fc / (dist + 1e-6f);
    float two_c = 2.f * c1;
    float sm = 0.f, sn = s1;
    r[0] = rs * sn;
    #pragma unroll
    for (int n = 1; n < 6; n++) {
        float sx = two_c * sn - sm;
        sm = sn; sn = sx;
        r[n] = rs * sx;
    }
}

#define LDSM4(r0,r1,r2,r3,addr) \
    asm volatile("ldmatrix.sync.aligned.m8n8.x4.shared.b16 {%0,%1,%2,%3},[%4];" \
                 : "=r"(r0),"=r"(r1),"=r"(r2),"=r"(r3) : "r"(addr))
#define LDSM4T(r0,r1,r2,r3,addr) \
    asm volatile("ldmatrix.sync.aligned.m8n8.x4.trans.shared.b16 {%0,%1,%2,%3},[%4];" \
                 : "=r"(r0),"=r"(r1),"=r"(r2),"=r"(r3) : "r"(addr))
#define MMA16816(d,a0,a1,a2,a3,b0,b1) \
    asm volatile("mma.sync.aligned.m16n8k16.row.col.f32.bf16.bf16.f32 " \
                 "{%0,%1,%2,%3},{%4,%5,%6,%7},{%8,%9},{%0,%1,%2,%3};" \
                 : "+f"(d[0]),"+f"(d[1]),"+f"(d[2]),"+f"(d[3]) \
                 : "r"(a0),"r"(a1),"r"(a2),"r"(a3),"r"(b0),"r"(b1))

// zero only the counters (tiny, stays on capture stream before classify)
__global__ void k_zcnt() { g_ncnt = 0; g_fcnt = 0; }

// bulk zero of g_agg (off critical path, on side stream)
__global__ void k_zero_agg() {
    int i = blockIdx.x * 256 + threadIdx.x;
    ((float4*)g_agg)[i] = make_float4(0.f, 0.f, 0.f, 0.f);
}

__global__ void k_splitW(const float* __restrict__ We, const float* __restrict__ Wm,
                         const float* __restrict__ Wu, const float* __restrict__ Wo) {
    int b = blockIdx.x, tid = threadIdx.x;
    if (b < 128) {
        float v = (b < 124) ? We[b * 128 + tid] : 0.f;
        split1(v, g_WeH + b * 136 + tid, g_WeL + b * 136 + tid);
    } else if (b < 256) {
        int r = b - 128;
        split1(Wm[r * 128 + tid], g_WmH + r * 136 + tid, g_WmL + r * 136 + tid);
    } else if (b < 384) {
        int r = b - 256;
        split1(Wu[r * 128 + tid], g_WuH + r * 136 + tid, g_WuL + r * 136 + tid);
    } else if (b < 512) {
        int r = b - 384;
        split1(Wo[r * 128 + tid], g_WoH + r * 136 + tid, g_WoL + r * 136 + tid);
    } else {
        int r = b - 512;
        split1(We[(108 + r) * 128 + tid], g_WfH + r * 136 + tid, g_WfL + r * 136 + tid);
    }
}

__global__ void k_classify(const int* __restrict__ ei, const float* __restrict__ pos) {
    int e = blockIdx.x * 256 + threadIdx.x;
    bool valid = e < NE;
    int ee = valid ? e : NE - 1;
    int j = ei[ee], i = ei[NE + ee];
    F3 d = sub3(ld3(pos, j), ld3(pos, i));
    float dist = sqrtf(dot3(d, d));
    bool far_ = valid && ((dist / 11.5f) >= 1.f);
    bool near_ = valid && !far_;
    int lane = threadIdx.x & 31;
    unsigned bf = __ballot_sync(0xffffffffu, far_);
    unsigned bn = __ballot_sync(0xffffffffu, near_);
    if (bf) {
        int src = __ffs(bf) - 1;
        int base = 0;
        if (lane == src) base = atomicAdd(&g_fcnt, __popc(bf));
        base = __shfl_sync(0xffffffffu, base, src);
        if (far_) g_fJI[base + __popc(bf & ((1u << lane) - 1))] = make_int2(j, i);
    }
    if (bn) {
        int src = __ffs(bn) - 1;
        int base = 0;
        if (lane == src) base = atomicAdd(&g_ncnt, __popc(bn));
        base = __shfl_sync(0xffffffffu, base, src);
        if (near_) g_nJI[base + __popc(bn & ((1u << lane) - 1))] = make_int2(j, i);
    }
}

__global__ void __launch_bounds__(256) k_embed(const int* __restrict__ z,
                                               const float* __restrict__ bb,
                                               const float* __restrict__ sc,
                                               const float* __restrict__ W,
                                               const float* __restrict__ b) {
    __shared__ float sW[40 * 64];
    __shared__ float sb[64];
    int tid = threadIdx.x;
    for (int idx = tid; idx < 40 * 64; idx += 256) sW[idx] = W[idx];
    if (tid < 64) sb[tid] = b[tid];
    __syncthreads();
    int node = blockIdx.x * 32 + (tid >> 3);
    int c0 = (tid & 7) * 8;
    if (node < NN) {
        float acc[8];
        int zz = z[node];
        #pragma unroll
        for (int cc = 0; cc < 8; cc++) acc[cc] = sb[c0 + cc] + sW[zz * 64 + c0 + cc];
        #pragma unroll
        for (int q = 0; q < 6; q++) {
            float v = bb[node * 6 + q];
            #pragma unroll
            for (int cc = 0; cc < 8; cc++) acc[cc] += v * sW[(26 + q) * 64 + c0 + cc];
        }
        #pragma unroll
        for (int q = 0; q < 8; q++) {
            float v = sc[node * 8 + q];
            #pragma unroll
            for (int cc = 0; cc < 8; cc++) acc[cc] += v * sW[(32 + q) * 64 + c0 + cc];
        }
        float* o = g_x + node * HH + c0;
        *(float4*)o = make_float4(acc[0], acc[1], acc[2], acc[3]);
        *(float4*)(o + 4) = make_float4(acc[4], acc[5], acc[6], acc[7]);
    }
}

__global__ void __launch_bounds__(256) k_esm_tc(const float* __restrict__ esm,
                                                const float* __restrict__ W,
                                                const float* __restrict__ b) {
    __shared__ __nv_bfloat16 AsH[128 * 40];
    __shared__ __nv_bfloat16 AsL[128 * 40];
    __shared__ __nv_bfloat16 BsH[32 * 72];
    __shared__ __nv_bfloat16 BsL[32 * 72];
    int tid = threadIdx.x;
    int m0 = blockIdx.x * 128;
    int wid = tid >> 5, lane = tid & 31;
    int warp_m = wid & 3, warp_n = wid >> 2;
    int arow = tid >> 1, ahalf = tid & 1;
    int grow = m0 + arow; if (grow >= NN) grow = NN - 1;
    const float* aptr = esm + (size_t)grow * 1280 + ahalf * 16;
    int brow = tid >> 3, bcol = (tid & 7) * 8;
    const float* bptr = W + brow * 64 + bcol;
    float acc[2][4][4];
    #pragma unroll
    for (int a_ = 0; a_ < 2; a_++)
        #pragma unroll
        for (int b_ = 0; b_ < 4; b_++)
            #pragma unroll
            for (int q = 0; q < 4; q++) acc[a_][b_][q] = 0.f;
    float4 ra[4]; float4 rb[2];
    #pragma unroll
    for (int q = 0; q < 4; q++) ra[q] = *(const float4*)(aptr + q * 4);
    rb[0] = *(const float4*)bptr; rb[1] = *(const float4*)(bptr + 4);
    int a_r = lane & 15, a_c = (lane >> 4) * 8;
    int b_k = lane & 15, b_n = (lane >> 4) * 8;
    for (int c = 0; c < 40; c++) {
        {
            float av[16] = {ra[0].x, ra[0].y, ra[0].z, ra[0].w,
                            ra[1].x, ra[1].y, ra[1].z, ra[1].w,
                            ra[2].x, ra[2].y, ra[2].z, ra[2].w,
                            ra[3].x, ra[3].y, ra[3].z, ra[3].w};
            __nv_bfloat162* dH = (__nv_bfloat162*)(AsH + arow * 40 + ahalf * 16);
            __nv_bfloat162* dL = (__nv_bfloat162*)(AsL + arow * 40 + ahalf * 16);
            #pragma unroll
            for (int q = 0; q < 8; q++) {
                __nv_bfloat162 h, l;
                split2(av[2 * q], av[2 * q + 1], h, l);
                dH[q] = h; dL[q] = l;
            }
            float bv[8] = {rb[0].x, rb[0].y, rb[0].z, rb[0].w,
                           rb[1].x, rb[1].y, rb[1].z, rb[1].w};
            __nv_bfloat162* eH = (__nv_bfloat162*)(BsH + brow * 72 + bcol);
            __nv_bfloat162* eL = (__nv_bfloat162*)(BsL + brow * 72 + bcol);
            #pragma unroll
            for (int q = 0; q < 4; q++) {
                __nv_bfloat162 h, l;
                split2(bv[2 * q], bv[2 * q + 1], h, l);
                eH[q] = h; eL[q] = l;
            }
        }
        __syncthreads();
        if (c < 39) {
            aptr += 32; bptr += 32 * 64;
            #pragma unroll
            for (int q = 0; q < 4; q++) ra[q] = *(const float4*)(aptr + q * 4);
            rb[0] = *(const float4*)bptr; rb[1] = *(const float4*)(bptr + 4);
        }
        #pragma unroll
        for (int ks = 0; ks < 2; ks++) {
            unsigned ah[2][4], al[2][4], bh[2][4], bl[2][4];
            #pragma unroll
            for (int mt = 0; mt < 2; mt++) {
                int row = warp_m * 32 + mt * 16 + a_r;
                int col = ks * 16 + a_c;
                LDSM4(ah[mt][0], ah[mt][1], ah[mt][2], ah[mt][3], sptr(AsH + row * 40 + col));
                LDSM4(al[mt][0], al[mt][1], al[mt][2], al[mt][3], sptr(AsL + row * 40 + col));
            }
            #pragma unroll
            for (int g = 0; g < 2; g++) {
                int kk = ks * 16 + b_k;
                int nn = warp_n * 32 + g * 16 + b_n;
                LDSM4T(bh[g][0], bh[g][1], bh[g][2], bh[g][3], sptr(BsH + kk * 72 + nn));
                LDSM4T(bl[g][0], bl[g][1], bl[g][2], bl[g][3], sptr(BsL + kk * 72 + nn));
            }
            #pragma unroll
            for (int mt = 0; mt < 2; mt++)
                #pragma unroll
                for (int nt = 0; nt < 4; nt++) {
                    int g = nt >> 1, h = (nt & 1) * 2;
                    MMA16816(acc[mt][nt], ah[mt][0], ah[mt][1], ah[mt][2], ah[mt][3],
                             bh[g][h], bh[g][h + 1]);
                    MMA16816(acc[mt][nt], ah[mt][0], ah[mt][1], ah[mt][2], ah[mt][3],
                             bl[g][h], bl[g][h + 1]);
                    MMA16816(acc[mt][nt], al[mt][0], al[mt][1], al[mt][2], al[mt][3],
                             bh[g][h], bh[g][h + 1]);
                }
        }
        __syncthreads();
    }
    #pragma unroll
    for (int mt = 0; mt < 2; mt++)
        #pragma unroll
        for (int nt = 0; nt < 4; nt++) {
            int row = m0 + warp_m * 32 + mt * 16 + (lane >> 2);
            int col = warp_n * 32 + nt * 8 + (lane & 3) * 2;
            if (row < NN) {
                g_x[row * HH + 64 + col] = acc[mt][nt][0] + b[col];
                g_x[row * HH + 64 + col + 1] = acc[mt][nt][1] + b[col + 1];
            }
            if (row + 8 < NN) {
                g_x[(row + 8) * HH + 64 + col] = acc[mt][nt][2] + b[col];
                g_x[(row + 8) * HH + 64 + col + 1] = acc[mt][nt][3] + b[col + 1];
            }
        }
}

// core mma over staged A/B (shared by gemm kernels)
__device__ __forceinline__ void mma128(const __nv_bfloat16* AsH, const __nv_bfloat16* AsL,
                                       const __nv_bfloat16* BsH, const __nv_bfloat16* BsL,
                                       float acc[2][8][4], int warp_m, int warp_n, int lane) {
    int a_r = lane & 15, a_c = (lane >> 4) * 8;
    int b_k = lane & 15, b_n = (lane >> 4) * 8;
    #pragma unroll
    for (int ks = 0; ks < 8; ks++) {
        unsigned ah[2][4], al[2][4];
        #pragma unroll
        for (int mt = 0; mt < 2; mt++) {
            int row = warp_m * 32 + mt * 16 + a_r;
            int col = ks * 16 + a_c;
            LDSM4(ah[mt][0], ah[mt][1], ah[mt][2], ah[mt][3], sptr(AsH + row * 136 + col));
            LDSM4(al[mt][0], al[mt][1], al[mt][2], al[mt][3], sptr(AsL + row * 136 + col));
        }
        #pragma unroll
        for (int g = 0; g < 4; g++) {
            unsigned bh[4], bl[4];
            int kk = ks * 16 + b_k;
            int nn = warp_n * 64 + g * 16 + b_n;
            LDSM4T(bh[0], bh[1], bh[2], bh[3], sptr(BsH + kk * 136 + nn));
            LDSM4T(bl[0], bl[1], bl[2], bl[3], sptr(BsL + kk * 136 + nn));
            #pragma unroll
            for (int mt = 0; mt < 2; mt++)
                #pragma unroll
                for (int t8 = 0; t8 < 2; t8++) {
                    int h = t8 * 2;
                    float* d = acc[mt][g * 2 + t8];
                    MMA16816(d, ah[mt][0], ah[mt][1], ah[mt][2], ah[mt][3], bh[h], bh[h + 1]);
                    MMA16816(d, ah[mt][0], ah[mt][1], ah[mt][2], ah[mt][3], bl[h], bl[h + 1]);
                    MMA16816(d, al[mt][0], al[mt][1], al[mt][2], al[mt][3], bh[h], bh[h + 1]);
                }
        }
    }
}

// gemm0: xm = swish(x @ W_msg)
__global__ void __launch_bounds__(256) k_gemm0_tc() {
    extern __shared__ __align__(16) char smraw[];
    __nv_bfloat16* AsH = (__nv_bfloat16*)smraw;
    __nv_bfloat16* AsL = AsH + 128 * 136;
    __nv_bfloat16* BsH = AsL + 128 * 136;
    __nv_bfloat16* BsL = BsH + 128 * 136;
    int tid = threadIdx.x;
    int m0 = blockIdx.x * 128;
    int wid = tid >> 5, lane = tid & 31;
    int warp_m = wid & 3, warp_n = wid >> 2;
    {
        const uint4* sH = (const uint4*)g_WmH;
        const uint4* sL = (const uint4*)g_WmL;
        uint4* dH = (uint4*)BsH;
        uint4* dL = (uint4*)BsL;
        for (int idx = tid; idx < 2176; idx += 256) { dH[idx] = sH[idx]; dL[idx] = sL[idx]; }
    }
    {
        int row = tid >> 1, half = tid & 1;
        int grow = m0 + row; if (grow >= NN) grow = NN - 1;
        const float* ap = g_x + grow * HH + half * 64;
        __nv_bfloat162* dH = (__nv_bfloat162*)(AsH + row * 136 + half * 64);
        __nv_bfloat162* dL = (__nv_bfloat162*)(AsL + row * 136 + half * 64);
        #pragma unroll
        for (int q = 0; q < 16; q++) {
            float4 v = ((const float4*)ap)[q];
            __nv_bfloat162 h, l;
            split2(v.x, v.y, h, l); dH[2 * q] = h; dL[2 * q] = l;
            split2(v.z, v.w, h, l); dH[2 * q + 1] = h; dL[2 * q + 1] = l;
        }
    }
    __syncthreads();
    float acc[2][8][4];
    #pragma unroll
    for (int a_ = 0; a_ < 2; a_++)
        #pragma unroll
        for (int b_ = 0; b_ < 8; b_++)
            #pragma unroll
            for (int q = 0; q < 4; q++) acc[a_][b_][q] = 0.f;
    mma128(AsH, AsL, BsH, BsL, acc, warp_m, warp_n, lane);
    #pragma unroll
    for (int mt = 0; mt < 2; mt++)
        #pragma unroll
        for (int nt = 0; nt < 8; nt++) {
            int row = m0 + warp_m * 32 + mt * 16 + (lane >> 2);
            int col = warp_n * 64 + nt * 8 + (lane & 3) * 2;
            float* d = acc[mt][nt];
            #pragma unroll
            for (int rr = 0; rr < 2; rr++) {
                int r = row + rr * 8;
                if (r < NN)
                    *(float2*)(g_xm + r * HH + col) =
                        make_float2(swishf(d[rr * 2]), swishf(d[rr * 2 + 1]));
            }
        }
}

// fused gemm1+gemm2: xe = x + swish(agg@W_upd); h0 = relu(xe@W_o0 + b) -> g_agg
__global__ void __launch_bounds__(256) k_gemm12_tc(const float* __restrict__ bias) {
    extern __shared__ __align__(16) char smraw[];
    __nv_bfloat16* AsH = (__nv_bfloat16*)smraw;
    __nv_bfloat16* AsL = AsH + 128 * 136;
    __nv_bfloat16* BsH = AsL + 128 * 136;
    __nv_bfloat16* BsL = BsH + 128 * 136;
    int tid = threadIdx.x;
    int m0 = blockIdx.x * 128;
    int wid = tid >> 5, lane = tid & 31;
    int warp_m = wid & 3, warp_n = wid >> 2;
    {
        const uint4* sH = (const uint4*)g_WuH;
        const uint4* sL = (const uint4*)g_WuL;
        uint4* dH = (uint4*)BsH;
        uint4* dL = (uint4*)BsL;
        for (int idx = tid; idx < 2176; idx += 256) { dH[idx] = sH[idx]; dL[idx] = sL[idx]; }
    }
    {
        int row = tid >> 1, half = tid & 1;
        int grow = m0 + row; if (grow >= NN) grow = NN - 1;
        const float* ap = g_agg + grow * HH + half * 64;
        __nv_bfloat162* dH = (__nv_bfloat162*)(AsH + row * 136 + half * 64);
        __nv_bfloat162* dL = (__nv_bfloat162*)(AsL + row * 136 + half * 64);
        #pragma unroll
        for (int q = 0; q < 16; q++) {
            float4 v = ((const float4*)ap)[q];
            __nv_bfloat162 h, l;
            split2(v.x, v.y, h, l); dH[2 * q] = h; dL[2 * q] = l;
            split2(v.z, v.w, h, l); dH[2 * q + 1] = h; dL[2 * q + 1] = l;
        }
    }
    __syncthreads();
    float acc[2][8][4];
    #pragma unroll
    for (int a_ = 0; a_ < 2; a_++)
        #pragma unroll
        for (int b_ = 0; b_ < 8; b_++)
            #pragma unroll
            for (int q = 0; q < 4; q++) acc[a_][b_][q] = 0.f;
    mma128(AsH, AsL, BsH, BsL, acc, warp_m, warp_n, lane);
    __syncthreads();
    #pragma unroll
    for (int mt = 0; mt < 2; mt++)
        #pragma unroll
        for (int nt = 0; nt < 8; nt++) {
            int rloc = warp_m * 32 + mt * 16 + (lane >> 2);
            int col = warp_n * 64 + nt * 8 + (lane & 3) * 2;
            float* d = acc[mt][nt];
            #pragma unroll
            for (int rr = 0; rr < 2; rr++) {
                int rl = rloc + rr * 8;
                int gr = m0 + rl; if (gr >= NN) gr = NN - 1;
                float2 xv = *(const float2*)(g_x + gr * HH + col);
                float e0 = xv.x + swishf(d[rr * 2]);
                float e1 = xv.y + swishf(d[rr * 2 + 1]);
                __nv_bfloat162 h, l;
                split2(e0, e1, h, l);
                *(__nv_bfloat162*)(AsH + rl * 136 + col) = h;
                *(__nv_bfloat162*)(AsL + rl * 136 + col) = l;
            }
        }
    {
        const uint4* sH = (const uint4*)g_WoH;
        const uint4* sL = (const uint4*)g_WoL;
        uint4* dH = (uint4*)BsH;
        uint4* dL = (uint4*)BsL;
        for (int idx = tid; idx < 2176; idx += 256) { dH[idx] = sH[idx]; dL[idx] = sL[idx]; }
    }
    __syncthreads();
    #pragma unroll
    for (int a_ = 0; a_ < 2; a_++)
        #pragma unroll
        for (int b_ = 0; b_ < 8; b_++)
            #pragma unroll
            for (int q = 0; q < 4; q++) acc[a_][b_][q] = 0.f;
    mma128(AsH, AsL, BsH, BsL, acc, warp_m, warp_n, lane);
    #pragma unroll
    for (int mt = 0; mt < 2; mt++)
        #pragma unroll
        for (int nt = 0; nt < 8; nt++) {
            int row = m0 + warp_m * 32 + mt * 16 + (lane >> 2);
            int col = warp_n * 64 + nt * 8 + (lane & 3) * 2;
            float* d = acc[mt][nt];
            #pragma unroll
            for (int rr = 0; rr < 2; rr++) {
                int r = row + rr * 8;
                if (r < NN)
                    *(float2*)(g_agg + r * HH + col) =
                        make_float2(fmaxf(d[rr * 2] + bias[col], 0.f),
                                    fmaxf(d[rr * 2 + 1] + bias[col + 1], 0.f));
            }
        }
}

__device__ __forceinline__ void edge_scatter(float acc[2][8][4], const int* js, const int* is_,
                                             int warp_m, int warp_n, int lane) {
    #pragma unroll
    for (int mt = 0; mt < 2; mt++)
        #pragma unroll
        for (int nt = 0; nt < 8; nt++) {
            int el = warp_m * 32 + mt * 16 + (lane >> 2);
            int col = warp_n * 64 + nt * 8 + (lane & 3) * 2;
            float* d = acc[mt][nt];
            #pragma unroll
            for (int rr = 0; rr < 2; rr++) {
                int e = el + rr * 8;
                int j = js[e];
                if (j >= 0) {
                    int i = is_[e];
                    float2 xv = *(const float2*)(g_xm + j * HH + col);
                    float m0 = swishf(d[rr * 2]) * xv.x;
                    float m1 = swishf(d[rr * 2 + 1]) * xv.y;
                    asm volatile("red.global.add.v2.f32 [%0], {%1,%2};"
                                 :: "l"(g_agg + i * HH + col), "f"(m0), "f"(m1) : "memory");
                }
            }
        }
}

// near edges: persistent blocks, W staged once, geometry split across 2 threads/edge
__global__ void __launch_bounds__(256) k_edge_near_tc(const float* __restrict__ pos,
                                                      const float* __restrict__ posn,
                                                      const float* __restrict__ posc) {
    int cnt = g_ncnt;
    extern __shared__ __align__(16) char smraw[];
    __nv_bfloat16* WsH = (__nv_bfloat16*)smraw;
    __nv_bfloat16* WsL = WsH + 128 * 136;
    __nv_bfloat16* FsH = WsL + 128 * 136;
    __nv_bfloat16* FsL = FsH + 128 * 136;
    int* js = (int*)(FsL + 128 * 136);
    int* is_ = js + 128;
    float* freqs = (float*)(is_ + 128);
    int tid = threadIdx.x;
    int wid = tid >> 5, lane = tid & 31;
    int warp_m = wid & 3, warp_n = wid >> 2;
    int e = tid & 127, role = tid >> 7;

    {
        const uint4* sH = (const uint4*)g_WeH;
        const uint4* sL = (const uint4*)g_WeL;
        uint4* dH = (uint4*)WsH;
        uint4* dL = (uint4*)WsL;
        for (int idx = tid; idx < 2176; idx += 256) { dH[idx] = sH[idx]; dL[idx] = sL[idx]; }
    }
    if (tid < 8) {
        float t = (float)(2 * tid) * (float)(-0.5756462732485115);
        freqs[tid] = (float)exp((double)t);
    }

    for (int t0 = blockIdx.x * 128; t0 < cnt; t0 += gridDim.x * 128) {
        __syncthreads();
        {
            int idx = t0 + e;
            bool valid = idx < cnt;
            int2 ji = g_nJI[valid ? idx : cnt - 1];
            int j = ji.x, i = ji.y;
            if (role == 0) { js[e] = valid ? j : -1; is_[e] = i; }
            __nv_bfloat16* fH = FsH + e * 136;
            __nv_bfloat16* fL = FsL + e * 136;
            F3 pi_ = ld3(pos, i), pj = ld3(pos, j);
            F3 vji = sub3(pj, pi_);
            float dist = sqrtf(dot3(vji, vji));
            float u = fminf(dist / 11.5f, 1.f);
            float r[6];
            radial6(u, dist, r);
            if (role == 0) {
                int r0 = (i == 0) ? NN - 1 : i - 1;
                int r1 = (i == NN - 1) ? 0 : i + 1;
                F3 vr0 = sub3(ld3(pos, r0), pi_);
                F3 vr1 = sub3(ld3(pos, r1), pi_);
                float a = dot3(vji, vr0);
                F3 cr = crs3(vji, vr0);
                float b2 = dot3(cr, cr);
                float ct1 = a * rsqrtf(fmaxf(a * a + b2, 1e-30f));
                float ct2 = 2.f * ct1 * ct1 - 1.f;
                F3 p1 = crs3(vr0, vr1), p2 = crs3(vr0, vji);
                float ap = dot3(p1, p2);
                F3 c12 = crs3(p1, p2);
                float bp = dot3(c12, vr0) / (sqrtf(dot3(vr0, vr0)) + 1e-7f);
                float cp1 = ap * rsqrtf(fmaxf(ap * ap + bp * bp, 1e-30f));
                float cp2 = 2.f * cp1 * cp1 - 1.f;
                float ct[3] = {1.f, ct1, ct2};
                float cp[3] = {1.f, cp1, cp2};
                #pragma unroll
                for (int n = 0; n < 6; n++)
                    #pragma unroll
                    for (int l = 0; l < 3; l++) {
                        float rl = r[n] * ct[l];
                        #pragma unroll
                        for (int m = 0; m < 3; m++) {
                            int k = n * 9 + l * 3 + m;
                            split1(rl * cp[m], fH + k, fL + k);
                        }
                    }
                float dpe = (float)(j - i);
                #pragma unroll
                for (int kk = 0; kk < 8; kk++) {
                    float s, c;
                    sincosf(dpe * freqs[kk], &s, &c);
                    split1(c, fH + 108 + kk, fL + 108 + kk);
                    split1(s, fH + 116 + kk, fL + 116 + kk);
                }
            } else {
                F3 o1x = sub3(ld3(posn, i), pi_);
                F3 o1z = crs3(o1x, crs3(o1x, sub3(ld3(posc, i), pi_)));
                float o1zl = sqrtf(dot3(o1z, o1z)) + 1e-7f;
                F3 o2x = sub3(ld3(posn, j), pj);
                F3 o2z = crs3(o2x, crs3(o2x, sub3(ld3(posc, j), pj)));
                float o2zl = sqrtf(dot3(o2z, o2z)) + 1e-7f;
                F3 nv = crs3(o1z, o2z);
                float a1 = dot3(o1x, nv);
                float b1 = dot3(crs3(o1x, nv), o1z) / o1zl;
                float cA10 = a1 * rsqrtf(fmaxf(a1 * a1 + b1 * b1, 1e-30f));
                float cA11 = 2.f * cA10 * cA10 - 1.f;
                float a2 = dot3(o1z, o2z);
                float b2v = sqrtf(dot3(nv, nv));
                float cA20 = a2 * rsqrtf(fmaxf(a2 * a2 + b2v * b2v, 1e-30f));
                float cA21 = 2.f * cA20 * cA20 - 1.f;
                float a3 = dot3(nv, o2x);
                float b3 = dot3(crs3(nv, o2x), o2z) / o2zl;
                float cA30 = a3 * rsqrtf(fmaxf(a3 * a3 + b3 * b3, 1e-30f));
                float cA31 = 2.f * cA30 * cA30 - 1.f;
                float cA[3][3] = {{1.f, cA10, cA11}, {1.f, cA20, cA21}, {1.f, cA30, cA31}};
                #pragma unroll
                for (int t = 0; t < 3; t++)
                    #pragma unroll
                    for (int n = 0; n < 6; n++)
                        #pragma unroll
                        for (int l = 0; l < 3; l++) {
                            int k = 54 + t * 18 + n * 3 + l;
                            split1(r[n] * cA[t][l], fH + k, fL + k);
                        }
                __nv_bfloat16 zb = __float2bfloat16_rn(0.f);
                #pragma unroll
                for (int k = 124; k < 128; k++) { fH[k] = zb; fL[k] = zb; }
            }
        }
        __syncthreads();

        float acc[2][8][4];
        #pragma unroll
        for (int a_ = 0; a_ < 2; a_++)
            #pragma unroll
            for (int b_ = 0; b_ < 8; b_++)
                #pragma unroll
                for (int q = 0; q < 4; q++) acc[a_][b_][q] = 0.f;
        mma128(FsH, FsL, WsH, WsL, acc, warp_m, warp_n, lane);
        edge_scatter(acc, js, is_, warp_m, warp_n, lane);
    }
}

// far edges: persistent blocks (small smem), PE split across 2 threads/edge
__global__ void __launch_bounds__(256) k_edge_far_tc() {
    int cnt = g_fcnt;
    __shared__ __align__(16) __nv_bfloat16 WsH[16 * 136], WsL[16 * 136];
    __shared__ __align__(16) __nv_bfloat16 FsH[128 * 24], FsL[128 * 24];
    __shared__ int js[128], is_[128];
    __shared__ float freqs[8];
    int tid = threadIdx.x;
    int wid = tid >> 5, lane = tid & 31;
    int warp_m = wid & 3, warp_n = wid >> 2;
    int e = tid & 127, role = tid >> 7;

    {
        const uint4* sH = (const uint4*)g_WfH;
        const uint4* sL = (const uint4*)g_WfL;
        uint4* dH = (uint4*)WsH;
        uint4* dL = (uint4*)WsL;
        for (int idx = tid; idx < 272; idx += 256) { dH[idx] = sH[idx]; dL[idx] = sL[idx]; }
    }
    if (tid < 8) {
        float t = (float)(2 * tid) * (float)(-0.5756462732485115);
        freqs[tid] = (float)exp((double)t);
    }

    int a_r = lane & 15, a_c = (lane >> 4) * 8;
    int b_k = lane & 15, b_n = (lane >> 4) * 8;

    for (int t0 = blockIdx.x * 128; t0 < cnt; t0 += gridDim.x * 128) {
        __syncthreads();
        {
            int idx = t0 + e;
            bool valid = idx < cnt;
            int2 ji = g_fJI[valid ? idx : cnt - 1];
            int j = ji.x, i = ji.y;
            if (role == 0) { js[e] = valid ? j : -1; is_[e] = i; }
            float dpe = (float)(j - i);
            __nv_bfloat16* fH = FsH + e * 24;
            __nv_bfloat16* fL = FsL + e * 24;
            #pragma unroll
            for (int q = 0; q < 4; q++) {
                int kk = role * 4 + q;
                float s, c;
                sincosf(dpe * freqs[kk], &s, &c);
                split1(c, fH + kk, fL + kk);
                split1(s, fH + 8 + kk, fL + 8 + kk);
            }
        }
        __syncthreads();

        float acc[2][8][4];
        #pragma unroll
        for (int a_ = 0; a_ < 2; a_++)
            #pragma unroll
            for (int b_ = 0; b_ < 8; b_++)
                #pragma unroll
                for (int q = 0; q < 4; q++) acc[a_][b_][q] = 0.f;
        unsigned ah[2][4], al[2][4];
        #pragma unroll
        for (int mt = 0; mt < 2; mt++) {
            int row = warp_m * 32 + mt * 16 + a_r;
            LDSM4(ah[mt][0], ah[mt][1], ah[mt][2], ah[mt][3], sptr(FsH + row * 24 + a_c));
            LDSM4(al[mt][0], al[mt][1], al[mt][2], al[mt][3], sptr(FsL + row * 24 + a_c));
        }
        #pragma unroll
        for (int g = 0; g < 4; g++) {
            unsigned bh[4], bl[4];
            int nn = warp_n * 64 + g * 16 + b_n;
            LDSM4T(bh[0], bh[1], bh[2], bh[3], sptr(WsH + b_k * 136 + nn));
            LDSM4T(bl[0], bl[1], bl[2], bl[3], sptr(WsL + b_k * 136 + nn));
            #pragma unroll
            for (int mt = 0; mt < 2; mt++)
                #pragma unroll
                for (int t8 = 0; t8 < 2; t8++) {
                    int h = t8 * 2;
                    float* d = acc[mt][g * 2 + t8];
                    MMA16816(d, ah[mt][0], ah[mt][1], ah[mt][2], ah[mt][3], bh[h], bh[h + 1]);
                    MMA16816(d, ah[mt][0], ah[mt][1], ah[mt][2], ah[mt][3], bl[h], bl[h + 1]);
                    MMA16816(d, al[mt][0], al[mt][1], al[mt][2], al[mt][3], bh[h], bh[h + 1]);
                }
        }
        edge_scatter(acc, js, is_, warp_m, warp_n, lane);
    }
}

__global__ void __launch_bounds__(256) k_nodehead(const float* __restrict__ W0,
                                                  const float* __restrict__ b0,
                                                  const float* __restrict__ Wf,
                                                  const float* __restrict__ bf,
                                                  float* __restrict__ out2) {
    __shared__ float sW[4096];
    __shared__ float sb[32], sWf[64], sbf[2];
    int tid = threadIdx.x;
    for (int idx = tid; idx < 4096; idx += 256) sW[idx] = W0[idx];
    if (tid < 32) sb[tid] = b0[tid];
    if (tid < 64) sWf[tid] = Wf[tid];
    if (tid < 2) sbf[tid] = bf[tid];
    __syncthreads();
    int w = tid >> 5, lane = tid & 31;
    int n = blockIdx.x * 8 + w;
    if (n >= NN) return;
    const float* xr = g_x + n * HH;
    float acc = sb[lane];
    #pragma unroll 8
    for (int k = 0; k < 128; k++) acc += xr[k] * sW[k * 32 + lane];
    float xn = fmaxf(acc, 0.f);
    float v0 = xn * sWf[lane * 2], v1 = xn * sWf[lane * 2 + 1];
    #pragma unroll
    for (int off = 16; off > 0; off >>= 1) {
        v0 += __shfl_xor_sync(0xffffffffu, v0, off);
        v1 += __shfl_xor_sync(0xffffffffu, v1, off);
    }
    if (lane == 0) { out2[n * 2] = v0 + sbf[0]; out2[n * 2 + 1] = v1 + sbf[1]; }
}

__global__ void __launch_bounds__(256) k_final(const float* __restrict__ W1,
                                               const float* __restrict__ b1,
                                               const float* __restrict__ Wf,
                                               const float* __restrict__ bf,
                                               float* __restrict__ out) {
    __shared__ float sW[4096];
    __shared__ float sb[32], sWf[32];
    int tid = threadIdx.x;
    for (int idx = tid; idx < 4096; idx += 256) sW[idx] = W1[idx];
    if (tid < 32) { sb[tid] = b1[tid]; sWf[tid] = Wf[tid]; }
    __syncthreads();
    int w = tid >> 5, lane = tid & 31;
    int n = blockIdx.x * 8 + w;
    if (n >= NN) return;
    const float* hr = g_agg + n * HH;
    float acc = sb[lane];
    #pragma unroll 8
    for (int k = 0; k < 128; k++) acc += hr[k] * sW[k * 32 + lane];
    float v = fmaxf(acc, 0.f) * sWf[lane];
    #pragma unroll
    for (int off = 16; off > 0; off >>= 1) v += __shfl_xor_sync(0xffffffffu, v, off);
    if (lane == 0) out[n] = 1.f / (1.f + expf(-(v + bf[0])));
}

extern "C" void kernel_launch(void* const* d_in, const int* in_sizes, int n_in,
                              void* d_out, int out_size) {
    const int* z = (const int*)d_in[0];
    const float* pos = (const float*)d_in[1];
    const float* posn = (const float*)d_in[2];
    const float* posc = (const float*)d_in[3];
    const float* bb = (const float*)d_in[4];
    const float* sc = (const float*)d_in[5];
    const float* esm = (const float*)d_in[6];
    const int* ei = (const int*)d_in[8];
    const float* W_emb = (const float*)d_in[9];
    const float* b_emb = (const float*)d_in[10];
    const float* W_esm = (const float*)d_in[11];
    const float* b_esm = (const float*)d_in[12];
    const float* W_edge = (const float*)d_in[13];
    const float* W_msg = (const float*)d_in[14];
    const float* W_upd = (const float*)d_in[15];
    const float* W_o0 = (const float*)d_in[16];
    const float* b_o0 = (const float*)d_in[17];
    const float* W_o1 = (const float*)d_in[18];
    const float* b_o1 = (const float*)d_in[19];
    const float* W_of = (const float*)d_in[20];
    const float* b_of = (const float*)d_in[21];
    const float* W_n0 = (const float*)d_in[22];
    const float* b_n0 = (const float*)d_in[23];
    const float* W_nf = (const float*)d_in[24];
    const float* b_nf = (const float*)d_in[25];
    float* out = (float*)d_out;

    const int GEMM_SMEM = 4 * 128 * 136 * 2;                     // 139264
    const int NEAR_SMEM = 4 * 128 * 136 * 2 + 2 * 128 * 4 + 32;  // 140320
    static cudaStream_t s1 = nullptr, s2 = nullptr;
    static cudaEvent_t evA, evB, evC, evE, evG, evF, evZ;
    if (!s1) {
        cudaStreamCreateWithFlags(&s1, cudaStreamNonBlocking);
        cudaStreamCreateWithFlags(&s2, cudaStreamNonBlocking);
        cudaEventCreateWithFlags(&evA, cudaEventDisableTiming);
        cudaEventCreateWithFlags(&evB, cudaEventDisableTiming);
        cudaEventCreateWithFlags(&evC, cudaEventDisableTiming);
        cudaEventCreateWithFlags(&evE, cudaEventDisableTiming);
        cudaEventCreateWithFlags(&evG, cudaEventDisableTiming);
        cudaEventCreateWithFlags(&evF, cudaEventDisableTiming);
        cudaEventCreateWithFlags(&evZ, cudaEventDisableTiming);
        cudaFuncSetAttribute(k_gemm0_tc, cudaFuncAttributeMaxDynamicSharedMemorySize, GEMM_SMEM);
        cudaFuncSetAttribute(k_gemm12_tc, cudaFuncAttributeMaxDynamicSharedMemorySize, GEMM_SMEM);
        cudaFuncSetAttribute(k_edge_near_tc, cudaFuncAttributeMaxDynamicSharedMemorySize, NEAR_SMEM);
    }

    // fork: esm on s1 overlaps the prologue; bulk zero on s2
    cudaEventRecord(evA, 0);
    cudaStreamWaitEvent(s1, evA, 0);
    k_esm_tc<<<391, 256, 0, s1>>>(esm, W_esm, b_esm);
    cudaEventRecord(evC, s1);                         // esm done

    cudaStreamWaitEvent(s2, evA, 0);
    k_zero_agg<<<6250, 256, 0, s2>>>();
    cudaEventRecord(evZ, s2);                         // agg zeroed

    k_zcnt<<<1, 1>>>();                               // counters (before classify)
    k_classify<<<3907, 256>>>(ei, pos);
    k_splitW<<<528, 128>>>(W_edge, W_msg, W_upd, W_o0);
    k_embed<<<1563, 256>>>(z, bb, sc, W_emb, b_emb);
    cudaEventRecord(evB, 0);                          // prologue done

    // nodehead needs x (embed + esm); overlaps gemm0/edges
    cudaStreamWaitEvent(s1, evB, 0);
    k_nodehead<<<6250, 256, 0, s1>>>(W_n0, b_n0, W_nf, b_nf, out + NN);
    cudaEventRecord(evE, s1);

    cudaStreamWaitEvent(0, evC, 0);                   // gemm0 needs esm's half of x
    k_gemm0_tc<<<391, 256, GEMM_SMEM>>>();
    cudaEventRecord(evG, 0);                          // xm ready

    // far on s2 (after zero on s2, after gemm0) concurrent with near on stream 0
    cudaStreamWaitEvent(s2, evG, 0);
    k_edge_far_tc<<<444, 256, 0, s2>>>();
    cudaEventRecord(evF, s2);

    cudaStreamWaitEvent(0, evZ, 0);                   // near needs agg zeroed
    k_edge_near_tc<<<148, 256, NEAR_SMEM>>>(pos, posn, posc);
    cudaStreamWaitEvent(0, evF, 0);                   // join far before fused gemm
    k_gemm12_tc<<<391, 256, GEMM_SMEM>>>(b_o0);
    k_final<<<6250, 256>>>(W_o1, b_o1, W_of, b_of, out);
    cudaStreamWaitEvent(0, evE, 0);                   // join nodehead
}

// round 17
// speedup vs baseline: 1.1910x; 1.0840x over previous
#include <cuda_runtime.h>
#include <cuda_bf16.h>
#include <math.h>

#define NN 50000
#define NE 1000000
#define HH 128

__device__ float g_x[NN * HH];
__device__ float g_xm[NN * HH];
__device__ float g_agg[NN * HH];
__device__ int g_ncnt, g_fcnt;
__device__ int2 g_nJI[NE];
__device__ int2 g_fJI[NE];
// pre-split weights (bf16 hi/lo)
__device__ __nv_bfloat16 g_WeH[128 * 136], g_WeL[128 * 136];
__device__ __nv_bfloat16 g_WfH[16 * 136],  g_WfL[16 * 136];
__device__ __nv_bfloat16 g_WmH[128 * 136], g_WmL[128 * 136];
__device__ __nv_bfloat16 g_WuH[128 * 136], g_WuL[128 * 136];
__device__ __nv_bfloat16 g_WoH[128 * 136], g_WoL[128 * 136];
__device__ __nv_bfloat16 g_W1H[128 * 40],  g_W1L[128 * 40];   // W_o1 [128,32] pitch 40

__device__ __forceinline__ float swishf(float v) { return v / (1.f + expf(-v)); }

struct F3 { float x, y, z; };
__device__ __forceinline__ F3 mk3(float a, float b, float c) { F3 r; r.x=a; r.y=b; r.z=c; return r; }
__device__ __forceinline__ F3 sub3(F3 a, F3 b) { return mk3(a.x-b.x, a.y-b.y, a.z-b.z); }
__device__ __forceinline__ F3 crs3(F3 a, F3 b) {
    return mk3(a.y*b.z - a.z*b.y, a.z*b.x - a.x*b.z, a.x*b.y - a.y*b.x);
}
__device__ __forceinline__ float dot3(F3 a, F3 b) { return a.x*b.x + a.y*b.y + a.z*b.z; }
__device__ __forceinline__ F3 ld3(const float* __restrict__ p, int i) {
    return mk3(p[3*i], p[3*i+1], p[3*i+2]);
}
__device__ __forceinline__ unsigned sptr(const void* p) {
    return (unsigned)__cvta_generic_to_shared(p);
}
__device__ __forceinline__ void split2(float x0, float x1, __nv_bfloat162& h, __nv_bfloat162& l) {
    __nv_bfloat16 h0 = __float2bfloat16_rn(x0);
    __nv_bfloat16 h1 = __float2bfloat16_rn(x1);
    h = __halves2bfloat162(h0, h1);
    l = __halves2bfloat162(__float2bfloat16_rn(x0 - __bfloat162float(h0)),
                           __float2bfloat16_rn(x1 - __bfloat162float(h1)));
}
__device__ __forceinline__ void split1(float x, __nv_bfloat16* pH, __nv_bfloat16* pL) {
    __nv_bfloat16 h = __float2bfloat16_rn(x);
    *pH = h;
    *pL = __float2bfloat16_rn(x - __bfloat162float(h));
}
// radial basis via Chebyshev recurrence
__device__ __forceinline__ void radial6(float u, float dist, float* r) {
    float s1, c1;
    sincosf(3.14159274f * u, &s1, &c1);
    float fc = 0.5f * (c1 + 1.f);
    float rs = (float)0.41702882811414954 * fc / (dist + 1e-6f);
    float two_c = 2.f * c1;
    float sm = 0.f, sn = s1;
    r[0] = rs * sn;
    #pragma unroll
    for (int n = 1; n < 6; n++) {
        float sx = two_c * sn - sm;
        sm = sn; sn = sx;
        r[n] = rs * sx;
    }
}

#define LDSM4(r0,r1,r2,r3,addr) \
    asm volatile("ldmatrix.sync.aligned.m8n8.x4.shared.b16 {%0,%1,%2,%3},[%4];" \
                 : "=r"(r0),"=r"(r1),"=r"(r2),"=r"(r3) : "r"(addr))
#define LDSM4T(r0,r1,r2,r3,addr) \
    asm volatile("ldmatrix.sync.aligned.m8n8.x4.trans.shared.b16 {%0,%1,%2,%3},[%4];" \
                 : "=r"(r0),"=r"(r1),"=r"(r2),"=r"(r3) : "r"(addr))
#define MMA16816(d,a0,a1,a2,a3,b0,b1) \
    asm volatile("mma.sync.aligned.m16n8k16.row.col.f32.bf16.bf16.f32 " \
                 "{%0,%1,%2,%3},{%4,%5,%6,%7},{%8,%9},{%0,%1,%2,%3};" \
                 : "+f"(d[0]),"+f"(d[1]),"+f"(d[2]),"+f"(d[3]) \
                 : "r"(a0),"r"(a1),"r"(a2),"r"(a3),"r"(b0),"r"(b1))

__global__ void k_zcnt() { g_ncnt = 0; g_fcnt = 0; }

__global__ void k_zero_agg() {
    int i = blockIdx.x * 256 + threadIdx.x;
    ((float4*)g_agg)[i] = make_float4(0.f, 0.f, 0.f, 0.f);
}

__global__ void k_splitW(const float* __restrict__ We, const float* __restrict__ Wm,
                         const float* __restrict__ Wu, const float* __restrict__ Wo,
                         const float* __restrict__ Wo1) {
    int b = blockIdx.x, tid = threadIdx.x;
    if (b < 128) {
        float v = (b < 124) ? We[b * 128 + tid] : 0.f;
        split1(v, g_WeH + b * 136 + tid, g_WeL + b * 136 + tid);
    } else if (b < 256) {
        int r = b - 128;
        split1(Wm[r * 128 + tid], g_WmH + r * 136 + tid, g_WmL + r * 136 + tid);
    } else if (b < 384) {
        int r = b - 256;
        split1(Wu[r * 128 + tid], g_WuH + r * 136 + tid, g_WuL + r * 136 + tid);
    } else if (b < 512) {
        int r = b - 384;
        split1(Wo[r * 128 + tid], g_WoH + r * 136 + tid, g_WoL + r * 136 + tid);
    } else if (b < 528) {
        int r = b - 512;
        split1(We[(108 + r) * 128 + tid], g_WfH + r * 136 + tid, g_WfL + r * 136 + tid);
    } else {
        int r = b - 528;       // W_o1: 128 rows x 32 cols, pitch 40 (zero pad)
        float v = (tid < 32) ? Wo1[r * 32 + tid] : 0.f;
        if (tid < 40) split1(v, g_W1H + r * 40 + tid, g_W1L + r * 40 + tid);
    }
}

__global__ void k_classify(const int* __restrict__ ei, const float* __restrict__ pos) {
    int e = blockIdx.x * 256 + threadIdx.x;
    bool valid = e < NE;
    int ee = valid ? e : NE - 1;
    int j = ei[ee], i = ei[NE + ee];
    F3 d = sub3(ld3(pos, j), ld3(pos, i));
    float dist = sqrtf(dot3(d, d));
    bool far_ = valid && ((dist / 11.5f) >= 1.f);
    bool near_ = valid && !far_;
    int lane = threadIdx.x & 31;
    unsigned bf = __ballot_sync(0xffffffffu, far_);
    unsigned bn = __ballot_sync(0xffffffffu, near_);
    if (bf) {
        int src = __ffs(bf) - 1;
        int base = 0;
        if (lane == src) base = atomicAdd(&g_fcnt, __popc(bf));
        base = __shfl_sync(0xffffffffu, base, src);
        if (far_) g_fJI[base + __popc(bf & ((1u << lane) - 1))] = make_int2(j, i);
    }
    if (bn) {
        int src = __ffs(bn) - 1;
        int base = 0;
        if (lane == src) base = atomicAdd(&g_ncnt, __popc(bn));
        base = __shfl_sync(0xffffffffu, base, src);
        if (near_) g_nJI[base + __popc(bn & ((1u << lane) - 1))] = make_int2(j, i);
    }
}

__global__ void __launch_bounds__(256) k_embed(const int* __restrict__ z,
                                               const float* __restrict__ bb,
                                               const float* __restrict__ sc,
                                               const float* __restrict__ W,
                                               const float* __restrict__ b) {
    __shared__ float sW[40 * 64];
    __shared__ float sb[64];
    int tid = threadIdx.x;
    for (int idx = tid; idx < 40 * 64; idx += 256) sW[idx] = W[idx];
    if (tid < 64) sb[tid] = b[tid];
    __syncthreads();
    int node = blockIdx.x * 32 + (tid >> 3);
    int c0 = (tid & 7) * 8;
    if (node < NN) {
        float acc[8];
        int zz = z[node];
        #pragma unroll
        for (int cc = 0; cc < 8; cc++) acc[cc] = sb[c0 + cc] + sW[zz * 64 + c0 + cc];
        #pragma unroll
        for (int q = 0; q < 6; q++) {
            float v = bb[node * 6 + q];
            #pragma unroll
            for (int cc = 0; cc < 8; cc++) acc[cc] += v * sW[(26 + q) * 64 + c0 + cc];
        }
        #pragma unroll
        for (int q = 0; q < 8; q++) {
            float v = sc[node * 8 + q];
            #pragma unroll
            for (int cc = 0; cc < 8; cc++) acc[cc] += v * sW[(32 + q) * 64 + c0 + cc];
        }
        float* o = g_x + node * HH + c0;
        *(float4*)o = make_float4(acc[0], acc[1], acc[2], acc[3]);
        *(float4*)(o + 4) = make_float4(acc[4], acc[5], acc[6], acc[7]);
    }
}

__global__ void __launch_bounds__(256) k_esm_tc(const float* __restrict__ esm,
                                                const float* __restrict__ W,
                                                const float* __restrict__ b) {
    __shared__ __nv_bfloat16 AsH[128 * 40];
    __shared__ __nv_bfloat16 AsL[128 * 40];
    __shared__ __nv_bfloat16 BsH[32 * 72];
    __shared__ __nv_bfloat16 BsL[32 * 72];
    int tid = threadIdx.x;
    int m0 = blockIdx.x * 128;
    int wid = tid >> 5, lane = tid & 31;
    int warp_m = wid & 3, warp_n = wid >> 2;
    int arow = tid >> 1, ahalf = tid & 1;
    int grow = m0 + arow; if (grow >= NN) grow = NN - 1;
    const float* aptr = esm + (size_t)grow * 1280 + ahalf * 16;
    int brow = tid >> 3, bcol = (tid & 7) * 8;
    const float* bptr = W + brow * 64 + bcol;
    float acc[2][4][4];
    #pragma unroll
    for (int a_ = 0; a_ < 2; a_++)
        #pragma unroll
        for (int b_ = 0; b_ < 4; b_++)
            #pragma unroll
            for (int q = 0; q < 4; q++) acc[a_][b_][q] = 0.f;
    float4 ra[4]; float4 rb[2];
    #pragma unroll
    for (int q = 0; q < 4; q++) ra[q] = *(const float4*)(aptr + q * 4);
    rb[0] = *(const float4*)bptr; rb[1] = *(const float4*)(bptr + 4);
    int a_r = lane & 15, a_c = (lane >> 4) * 8;
    int b_k = lane & 15, b_n = (lane >> 4) * 8;
    for (int c = 0; c < 40; c++) {
        {
            float av[16] = {ra[0].x, ra[0].y, ra[0].z, ra[0].w,
                            ra[1].x, ra[1].y, ra[1].z, ra[1].w,
                            ra[2].x, ra[2].y, ra[2].z, ra[2].w,
                            ra[3].x, ra[3].y, ra[3].z, ra[3].w};
            __nv_bfloat162* dH = (__nv_bfloat162*)(AsH + arow * 40 + ahalf * 16);
            __nv_bfloat162* dL = (__nv_bfloat162*)(AsL + arow * 40 + ahalf * 16);
            #pragma unroll
            for (int q = 0; q < 8; q++) {
                __nv_bfloat162 h, l;
                split2(av[2 * q], av[2 * q + 1], h, l);
                dH[q] = h; dL[q] = l;
            }
            float bv[8] = {rb[0].x, rb[0].y, rb[0].z, rb[0].w,
                           rb[1].x, rb[1].y, rb[1].z, rb[1].w};
            __nv_bfloat162* eH = (__nv_bfloat162*)(BsH + brow * 72 + bcol);
            __nv_bfloat162* eL = (__nv_bfloat162*)(BsL + brow * 72 + bcol);
            #pragma unroll
            for (int q = 0; q < 4; q++) {
                __nv_bfloat162 h, l;
                split2(bv[2 * q], bv[2 * q + 1], h, l);
                eH[q] = h; eL[q] = l;
            }
        }
        __syncthreads();
        if (c < 39) {
            aptr += 32; bptr += 32 * 64;
            #pragma unroll
            for (int q = 0; q < 4; q++) ra[q] = *(const float4*)(aptr + q * 4);
            rb[0] = *(const float4*)bptr; rb[1] = *(const float4*)(bptr + 4);
        }
        #pragma unroll
        for (int ks = 0; ks < 2; ks++) {
            unsigned ah[2][4], al[2][4], bh[2][4], bl[2][4];
            #pragma unroll
            for (int mt = 0; mt < 2; mt++) {
                int row = warp_m * 32 + mt * 16 + a_r;
                int col = ks * 16 + a_c;
                LDSM4(ah[mt][0], ah[mt][1], ah[mt][2], ah[mt][3], sptr(AsH + row * 40 + col));
                LDSM4(al[mt][0], al[mt][1], al[mt][2], al[mt][3], sptr(AsL + row * 40 + col));
            }
            #pragma unroll
            for (int g = 0; g < 2; g++) {
                int kk = ks * 16 + b_k;
                int nn = warp_n * 32 + g * 16 + b_n;
                LDSM4T(bh[g][0], bh[g][1], bh[g][2], bh[g][3], sptr(BsH + kk * 72 + nn));
                LDSM4T(bl[g][0], bl[g][1], bl[g][2], bl[g][3], sptr(BsL + kk * 72 + nn));
            }
            #pragma unroll
            for (int mt = 0; mt < 2; mt++)
                #pragma unroll
                for (int nt = 0; nt < 4; nt++) {
                    int g = nt >> 1, h = (nt & 1) * 2;
                    MMA16816(acc[mt][nt], ah[mt][0], ah[mt][1], ah[mt][2], ah[mt][3],
                             bh[g][h], bh[g][h + 1]);
                    MMA16816(acc[mt][nt], ah[mt][0], ah[mt][1], ah[mt][2], ah[mt][3],
                             bl[g][h], bl[g][h + 1]);
                    MMA16816(acc[mt][nt], al[mt][0], al[mt][1], al[mt][2], al[mt][3],
                             bh[g][h], bh[g][h + 1]);
                }
        }
        __syncthreads();
    }
    #pragma unroll
    for (int mt = 0; mt < 2; mt++)
        #pragma unroll
        for (int nt = 0; nt < 4; nt++) {
            int row = m0 + warp_m * 32 + mt * 16 + (lane >> 2);
            int col = warp_n * 32 + nt * 8 + (lane & 3) * 2;
            if (row < NN) {
                g_x[row * HH + 64 + col] = acc[mt][nt][0] + b[col];
                g_x[row * HH + 64 + col + 1] = acc[mt][nt][1] + b[col + 1];
            }
            if (row + 8 < NN) {
                g_x[(row + 8) * HH + 64 + col] = acc[mt][nt][2] + b[col];
                g_x[(row + 8) * HH + 64 + col + 1] = acc[mt][nt][3] + b[col + 1];
            }
        }
}

// core mma over staged A/B
__device__ __forceinline__ void mma128(const __nv_bfloat16* AsH, const __nv_bfloat16* AsL,
                                       const __nv_bfloat16* BsH, const __nv_bfloat16* BsL,
                                       float acc[2][8][4], int warp_m, int warp_n, int lane) {
    int a_r = lane & 15, a_c = (lane >> 4) * 8;
    int b_k = lane & 15, b_n = (lane >> 4) * 8;
    #pragma unroll
    for (int ks = 0; ks < 8; ks++) {
        unsigned ah[2][4], al[2][4];
        #pragma unroll
        for (int mt = 0; mt < 2; mt++) {
            int row = warp_m * 32 + mt * 16 + a_r;
            int col = ks * 16 + a_c;
            LDSM4(ah[mt][0], ah[mt][1], ah[mt][2], ah[mt][3], sptr(AsH + row * 136 + col));
            LDSM4(al[mt][0], al[mt][1], al[mt][2], al[mt][3], sptr(AsL + row * 136 + col));
        }
        #pragma unroll
        for (int g = 0; g < 4; g++) {
            unsigned bh[4], bl[4];
            int kk = ks * 16 + b_k;
            int nn = warp_n * 64 + g * 16 + b_n;
            LDSM4T(bh[0], bh[1], bh[2], bh[3], sptr(BsH + kk * 136 + nn));
            LDSM4T(bl[0], bl[1], bl[2], bl[3], sptr(BsL + kk * 136 + nn));
            #pragma unroll
            for (int mt = 0; mt < 2; mt++)
                #pragma unroll
                for (int t8 = 0; t8 < 2; t8++) {
                    int h = t8 * 2;
                    float* d = acc[mt][g * 2 + t8];
                    MMA16816(d, ah[mt][0], ah[mt][1], ah[mt][2], ah[mt][3], bh[h], bh[h + 1]);
                    MMA16816(d, ah[mt][0], ah[mt][1], ah[mt][2], ah[mt][3], bl[h], bl[h + 1]);
                    MMA16816(d, al[mt][0], al[mt][1], al[mt][2], al[mt][3], bh[h], bh[h + 1]);
                }
        }
    }
}

// gemm0: xm = swish(x @ W_msg)
__global__ void __launch_bounds__(256) k_gemm0_tc() {
    extern __shared__ __align__(16) char smraw[];
    __nv_bfloat16* AsH = (__nv_bfloat16*)smraw;
    __nv_bfloat16* AsL = AsH + 128 * 136;
    __nv_bfloat16* BsH = AsL + 128 * 136;
    __nv_bfloat16* BsL = BsH + 128 * 136;
    int tid = threadIdx.x;
    int m0 = blockIdx.x * 128;
    int wid = tid >> 5, lane = tid & 31;
    int warp_m = wid & 3, warp_n = wid >> 2;
    {
        const uint4* sH = (const uint4*)g_WmH;
        const uint4* sL = (const uint4*)g_WmL;
        uint4* dH = (uint4*)BsH;
        uint4* dL = (uint4*)BsL;
        for (int idx = tid; idx < 2176; idx += 256) { dH[idx] = sH[idx]; dL[idx] = sL[idx]; }
    }
    {
        int row = tid >> 1, half = tid & 1;
        int grow = m0 + row; if (grow >= NN) grow = NN - 1;
        const float* ap = g_x + grow * HH + half * 64;
        __nv_bfloat162* dH = (__nv_bfloat162*)(AsH + row * 136 + half * 64);
        __nv_bfloat162* dL = (__nv_bfloat162*)(AsL + row * 136 + half * 64);
        #pragma unroll
        for (int q = 0; q < 16; q++) {
            float4 v = ((const float4*)ap)[q];
            __nv_bfloat162 h, l;
            split2(v.x, v.y, h, l); dH[2 * q] = h; dL[2 * q] = l;
            split2(v.z, v.w, h, l); dH[2 * q + 1] = h; dL[2 * q + 1] = l;
        }
    }
    __syncthreads();
    float acc[2][8][4];
    #pragma unroll
    for (int a_ = 0; a_ < 2; a_++)
        #pragma unroll
        for (int b_ = 0; b_ < 8; b_++)
            #pragma unroll
            for (int q = 0; q < 4; q++) acc[a_][b_][q] = 0.f;
    mma128(AsH, AsL, BsH, BsL, acc, warp_m, warp_n, lane);
    #pragma unroll
    for (int mt = 0; mt < 2; mt++)
        #pragma unroll
        for (int nt = 0; nt < 8; nt++) {
            int row = m0 + warp_m * 32 + mt * 16 + (lane >> 2);
            int col = warp_n * 64 + nt * 8 + (lane & 3) * 2;
            float* d = acc[mt][nt];
            #pragma unroll
            for (int rr = 0; rr < 2; rr++) {
                int r = row + rr * 8;
                if (r < NN)
                    *(float2*)(g_xm + r * HH + col) =
                        make_float2(swishf(d[rr * 2]), swishf(d[rr * 2 + 1]));
            }
        }
}

// fused gemm1+gemm2+head: xe = x + swish(agg@W_upd); h0 = relu(xe@W_o0+b);
// h1 = relu(h0@W_o1+b1); out = sigmoid(h1@W_of+bf)
__global__ void __launch_bounds__(256) k_gemm12_tc(const float* __restrict__ bias,
                                                   const float* __restrict__ b1,
                                                   const float* __restrict__ Wof,
                                                   const float* __restrict__ bf,
                                                   float* __restrict__ out) {
    extern __shared__ __align__(16) char smraw[];
    __nv_bfloat16* AsH = (__nv_bfloat16*)smraw;
    __nv_bfloat16* AsL = AsH + 128 * 136;
    __nv_bfloat16* BsH = AsL + 128 * 136;
    __nv_bfloat16* BsL = BsH + 128 * 136;
    // mma3 W_o1 staged at start of Bs; h1 buffer after it (aliases tail of BsH block)
    __nv_bfloat16* W1H = BsH;
    __nv_bfloat16* W1L = BsL;
    float* h1buf = (float*)((char*)BsH + 128 * 40 * 2);   // 128*33 floats = 16896B (fits)
    __shared__ float sb1[32], sWof[32], sbfv[1];
    int tid = threadIdx.x;
    int m0 = blockIdx.x * 128;
    int wid = tid >> 5, lane = tid & 31;
    int warp_m = wid & 3, warp_n = wid >> 2;
    if (tid < 32) { sb1[tid] = b1[tid]; sWof[tid] = Wof[tid]; }
    if (tid == 32) sbfv[0] = bf[0];
    {
        const uint4* sH = (const uint4*)g_WuH;
        const uint4* sL = (const uint4*)g_WuL;
        uint4* dH = (uint4*)BsH;
        uint4* dL = (uint4*)BsL;
        for (int idx = tid; idx < 2176; idx += 256) { dH[idx] = sH[idx]; dL[idx] = sL[idx]; }
    }
    {
        int row = tid >> 1, half = tid & 1;
        int grow = m0 + row; if (grow >= NN) grow = NN - 1;
        const float* ap = g_agg + grow * HH + half * 64;
        __nv_bfloat162* dH = (__nv_bfloat162*)(AsH + row * 136 + half * 64);
        __nv_bfloat162* dL = (__nv_bfloat162*)(AsL + row * 136 + half * 64);
        #pragma unroll
        for (int q = 0; q < 16; q++) {
            float4 v = ((const float4*)ap)[q];
            __nv_bfloat162 h, l;
            split2(v.x, v.y, h, l); dH[2 * q] = h; dL[2 * q] = l;
            split2(v.z, v.w, h, l); dH[2 * q + 1] = h; dL[2 * q + 1] = l;
        }
    }
    __syncthreads();
    float acc[2][8][4];
    #pragma unroll
    for (int a_ = 0; a_ < 2; a_++)
        #pragma unroll
        for (int b_ = 0; b_ < 8; b_++)
            #pragma unroll
            for (int q = 0; q < 4; q++) acc[a_][b_][q] = 0.f;
    mma128(AsH, AsL, BsH, BsL, acc, warp_m, warp_n, lane);
    __syncthreads();
    // epilogue1: xe = x + swish(acc) -> split into As; stage W_o0 into Bs
    #pragma unroll
    for (int mt = 0; mt < 2; mt++)
        #pragma unroll
        for (int nt = 0; nt < 8; nt++) {
            int rloc = warp_m * 32 + mt * 16 + (lane >> 2);
            int col = warp_n * 64 + nt * 8 + (lane & 3) * 2;
            float* d = acc[mt][nt];
            #pragma unroll
            for (int rr = 0; rr < 2; rr++) {
                int rl = rloc + rr * 8;
                int gr = m0 + rl; if (gr >= NN) gr = NN - 1;
                float2 xv = *(const float2*)(g_x + gr * HH + col);
                float e0 = xv.x + swishf(d[rr * 2]);
                float e1 = xv.y + swishf(d[rr * 2 + 1]);
                __nv_bfloat162 h, l;
                split2(e0, e1, h, l);
                *(__nv_bfloat162*)(AsH + rl * 136 + col) = h;
                *(__nv_bfloat162*)(AsL + rl * 136 + col) = l;
            }
        }
    {
        const uint4* sH = (const uint4*)g_WoH;
        const uint4* sL = (const uint4*)g_WoL;
        uint4* dH = (uint4*)BsH;
        uint4* dL = (uint4*)BsL;
        for (int idx = tid; idx < 2176; idx += 256) { dH[idx] = sH[idx]; dL[idx] = sL[idx]; }
    }
    __syncthreads();
    #pragma unroll
    for (int a_ = 0; a_ < 2; a_++)
        #pragma unroll
        for (int b_ = 0; b_ < 8; b_++)
            #pragma unroll
            for (int q = 0; q < 4; q++) acc[a_][b_][q] = 0.f;
    mma128(AsH, AsL, BsH, BsL, acc, warp_m, warp_n, lane);
    __syncthreads();
    // epilogue2: h0 = relu(acc + bias) -> split into As; stage W_o1 into Bs head
    #pragma unroll
    for (int mt = 0; mt < 2; mt++)
        #pragma unroll
        for (int nt = 0; nt < 8; nt++) {
            int rloc = warp_m * 32 + mt * 16 + (lane >> 2);
            int col = warp_n * 64 + nt * 8 + (lane & 3) * 2;
            float* d = acc[mt][nt];
            #pragma unroll
            for (int rr = 0; rr < 2; rr++) {
                int rl = rloc + rr * 8;
                float h0a = fmaxf(d[rr * 2] + bias[col], 0.f);
                float h0b = fmaxf(d[rr * 2 + 1] + bias[col + 1], 0.f);
                __nv_bfloat162 h, l;
                split2(h0a, h0b, h, l);
                *(__nv_bfloat162*)(AsH + rl * 136 + col) = h;
                *(__nv_bfloat162*)(AsL + rl * 136 + col) = l;
            }
        }
    {
        const uint4* sH = (const uint4*)g_W1H;
        const uint4* sL = (const uint4*)g_W1L;
        uint4* dH = (uint4*)W1H;
        uint4* dL = (uint4*)W1L;
        for (int idx = tid; idx < 640; idx += 256) { dH[idx] = sH[idx]; dL[idx] = sL[idx]; }
    }
    __syncthreads();
    // mma3: h1 = relu(h0 @ W_o1 + b1); each warp owns 16 rows, N=32, K=128
    {
        int a_r = lane & 15, a_c = (lane >> 4) * 8;
        int b_k = lane & 15, b_n = (lane >> 4) * 8;
        float a2[4][4];
        #pragma unroll
        for (int g = 0; g < 4; g++)
            #pragma unroll
            for (int q = 0; q < 4; q++) a2[g][q] = 0.f;
        #pragma unroll
        for (int ks = 0; ks < 8; ks++) {
            unsigned ah[4], al[4];
            int row = wid * 16 + a_r;
            int col = ks * 16 + a_c;
            LDSM4(ah[0], ah[1], ah[2], ah[3], sptr(AsH + row * 136 + col));
            LDSM4(al[0], al[1], al[2], al[3], sptr(AsL + row * 136 + col));
            #pragma unroll
            for (int g = 0; g < 2; g++) {
                unsigned bh[4], bl[4];
                int kk = ks * 16 + b_k;
                int nn = g * 16 + b_n;
                LDSM4T(bh[0], bh[1], bh[2], bh[3], sptr(W1H + kk * 40 + nn));
                LDSM4T(bl[0], bl[1], bl[2], bl[3], sptr(W1L + kk * 40 + nn));
                #pragma unroll
                for (int t8 = 0; t8 < 2; t8++) {
                    int h = t8 * 2;
                    float* d = a2[g * 2 + t8];
                    MMA16816(d, ah[0], ah[1], ah[2], ah[3], bh[h], bh[h + 1]);
                    MMA16816(d, ah[0], ah[1], ah[2], ah[3], bl[h], bl[h + 1]);
                    MMA16816(d, al[0], al[1], al[2], al[3], bh[h], bh[h + 1]);
                }
            }
        }
        __syncthreads();   // all warps done reading As/W1 before h1buf (aliases Bs tail)
        #pragma unroll
        for (int g = 0; g < 4; g++) {
            int col = g * 8 + (lane & 3) * 2;
            #pragma unroll
            for (int rr = 0; rr < 2; rr++) {
                int row = wid * 16 + (lane >> 2) + rr * 8;
                h1buf[row * 33 + col] = fmaxf(a2[g][rr * 2] + sb1[col], 0.f);
                h1buf[row * 33 + col + 1] = fmaxf(a2[g][rr * 2 + 1] + sb1[col + 1], 0.f);
            }
        }
    }
    __syncthreads();
    // final: out = sigmoid(h1 @ W_of + bf)
    if (tid < 128) {
        int r = m0 + tid;
        if (r < NN) {
            float s = sbfv[0];
            #pragma unroll 8
            for (int k = 0; k < 32; k++) s += h1buf[tid * 33 + k] * sWof[k];
            out[r] = 1.f / (1.f + expf(-s));
        }
    }
}

__device__ __forceinline__ void edge_scatter(float acc[2][8][4], const int* js, const int* is_,
                                             int warp_m, int warp_n, int lane) {
    #pragma unroll
    for (int mt = 0; mt < 2; mt++)
        #pragma unroll
        for (int nt = 0; nt < 8; nt++) {
            int el = warp_m * 32 + mt * 16 + (lane >> 2);
            int col = warp_n * 64 + nt * 8 + (lane & 3) * 2;
            float* d = acc[mt][nt];
            #pragma unroll
            for (int rr = 0; rr < 2; rr++) {
                int e = el + rr * 8;
                int j = js[e];
                if (j >= 0) {
                    int i = is_[e];
                    float2 xv = *(const float2*)(g_xm + j * HH + col);
                    float m0 = swishf(d[rr * 2]) * xv.x;
                    float m1 = swishf(d[rr * 2 + 1]) * xv.y;
                    asm volatile("red.global.add.v2.f32 [%0], {%1,%2};"
                                 :: "l"(g_agg + i * HH + col), "f"(m0), "f"(m1) : "memory");
                }
            }
        }
}

// near edges: persistent blocks, W staged once, geometry split across 2 threads/edge
__global__ void __launch_bounds__(256) k_edge_near_tc(const float* __restrict__ pos,
                                                      const float* __restrict__ posn,
                                                      const float* __restrict__ posc) {
    int cnt = g_ncnt;
    extern __shared__ __align__(16) char smraw[];
    __nv_bfloat16* WsH = (__nv_bfloat16*)smraw;
    __nv_bfloat16* WsL = WsH + 128 * 136;
    __nv_bfloat16* FsH = WsL + 128 * 136;
    __nv_bfloat16* FsL = FsH + 128 * 136;
    int* js = (int*)(FsL + 128 * 136);
    int* is_ = js + 128;
    float* freqs = (float*)(is_ + 128);
    int tid = threadIdx.x;
    int wid = tid >> 5, lane = tid & 31;
    int warp_m = wid & 3, warp_n = wid >> 2;
    int e = tid & 127, role = tid >> 7;

    {
        const uint4* sH = (const uint4*)g_WeH;
        const uint4* sL = (const uint4*)g_WeL;
        uint4* dH = (uint4*)WsH;
        uint4* dL = (uint4*)WsL;
        for (int idx = tid; idx < 2176; idx += 256) { dH[idx] = sH[idx]; dL[idx] = sL[idx]; }
    }
    if (tid < 8) {
        float t = (float)(2 * tid) * (float)(-0.5756462732485115);
        freqs[tid] = (float)exp((double)t);
    }

    for (int t0 = blockIdx.x * 128; t0 < cnt; t0 += gridDim.x * 128) {
        __syncthreads();
        {
            int idx = t0 + e;
            bool valid = idx < cnt;
            int2 ji = g_nJI[valid ? idx : cnt - 1];
            int j = ji.x, i = ji.y;
            if (role == 0) { js[e] = valid ? j : -1; is_[e] = i; }
            __nv_bfloat16* fH = FsH + e * 136;
            __nv_bfloat16* fL = FsL + e * 136;
            F3 pi_ = ld3(pos, i), pj = ld3(pos, j);
            F3 vji = sub3(pj, pi_);
            float dist = sqrtf(dot3(vji, vji));
            float u = fminf(dist / 11.5f, 1.f);
            float r[6];
            radial6(u, dist, r);
            if (role == 0) {
                int r0 = (i == 0) ? NN - 1 : i - 1;
                int r1 = (i == NN - 1) ? 0 : i + 1;
                F3 vr0 = sub3(ld3(pos, r0), pi_);
                F3 vr1 = sub3(ld3(pos, r1), pi_);
                float a = dot3(vji, vr0);
                F3 cr = crs3(vji, vr0);
                float b2 = dot3(cr, cr);
                float ct1 = a * rsqrtf(fmaxf(a * a + b2, 1e-30f));
                float ct2 = 2.f * ct1 * ct1 - 1.f;
                F3 p1 = crs3(vr0, vr1), p2 = crs3(vr0, vji);
                float ap = dot3(p1, p2);
                F3 c12 = crs3(p1, p2);
                float bp = dot3(c12, vr0) / (sqrtf(dot3(vr0, vr0)) + 1e-7f);
                float cp1 = ap * rsqrtf(fmaxf(ap * ap + bp * bp, 1e-30f));
                float cp2 = 2.f * cp1 * cp1 - 1.f;
                float ct[3] = {1.f, ct1, ct2};
                float cp[3] = {1.f, cp1, cp2};
                #pragma unroll
                for (int n = 0; n < 6; n++)
                    #pragma unroll
                    for (int l = 0; l < 3; l++) {
                        float rl = r[n] * ct[l];
                        #pragma unroll
                        for (int m = 0; m < 3; m++) {
                            int k = n * 9 + l * 3 + m;
                            split1(rl * cp[m], fH + k, fL + k);
                        }
                    }
                float dpe = (float)(j - i);
                #pragma unroll
                for (int kk = 0; kk < 8; kk++) {
                    float s, c;
                    sincosf(dpe * freqs[kk], &s, &c);
                    split1(c, fH + 108 + kk, fL + 108 + kk);
                    split1(s, fH + 116 + kk, fL + 116 + kk);
                }
            } else {
                F3 o1x = sub3(ld3(posn, i), pi_);
                F3 o1z = crs3(o1x, crs3(o1x, sub3(ld3(posc, i), pi_)));
                float o1zl = sqrtf(dot3(o1z, o1z)) + 1e-7f;
                F3 o2x = sub3(ld3(posn, j), pj);
                F3 o2z = crs3(o2x, crs3(o2x, sub3(ld3(posc, j), pj)));
                float o2zl = sqrtf(dot3(o2z, o2z)) + 1e-7f;
                F3 nv = crs3(o1z, o2z);
                float a1 = dot3(o1x, nv);
                float b1 = dot3(crs3(o1x, nv), o1z) / o1zl;
                float cA10 = a1 * rsqrtf(fmaxf(a1 * a1 + b1 * b1, 1e-30f));
                float cA11 = 2.f * cA10 * cA10 - 1.f;
                float a2 = dot3(o1z, o2z);
                float b2v = sqrtf(dot3(nv, nv));
                float cA20 = a2 * rsqrtf(fmaxf(a2 * a2 + b2v * b2v, 1e-30f));
                float cA21 = 2.f * cA20 * cA20 - 1.f;
                float a3 = dot3(nv, o2x);
                float b3 = dot3(crs3(nv, o2x), o2z) / o2zl;
                float cA30 = a3 * rsqrtf(fmaxf(a3 * a3 + b3 * b3, 1e-30f));
                float cA31 = 2.f * cA30 * cA30 - 1.f;
                float cA[3][3] = {{1.f, cA10, cA11}, {1.f, cA20, cA21}, {1.f, cA30, cA31}};
                #pragma unroll
                for (int t = 0; t < 3; t++)
                    #pragma unroll
                    for (int n = 0; n < 6; n++)
                        #pragma unroll
                        for (int l = 0; l < 3; l++) {
                            int k = 54 + t * 18 + n * 3 + l;
                            split1(r[n] * cA[t][l], fH + k, fL + k);
                        }
                __nv_bfloat16 zb = __float2bfloat16_rn(0.f);
                #pragma unroll
                for (int k = 124; k < 128; k++) { fH[k] = zb; fL[k] = zb; }
            }
        }
        __syncthreads();

        float acc[2][8][4];
        #pragma unroll
        for (int a_ = 0; a_ < 2; a_++)
            #pragma unroll
            for (int b_ = 0; b_ < 8; b_++)
                #pragma unroll
                for (int q = 0; q < 4; q++) acc[a_][b_][q] = 0.f;
        mma128(FsH, FsL, WsH, WsL, acc, warp_m, warp_n, lane);
        edge_scatter(acc, js, is_, warp_m, warp_n, lane);
    }
}

// far edges: persistent blocks (small smem), PE split across 2 threads/edge
__global__ void __launch_bounds__(256) k_edge_far_tc() {
    int cnt = g_fcnt;
    __shared__ __align__(16) __nv_bfloat16 WsH[16 * 136], WsL[16 * 136];
    __shared__ __align__(16) __nv_bfloat16 FsH[128 * 24], FsL[128 * 24];
    __shared__ int js[128], is_[128];
    __shared__ float freqs[8];
    int tid = threadIdx.x;
    int wid = tid >> 5, lane = tid & 31;
    int warp_m = wid & 3, warp_n = wid >> 2;
    int e = tid & 127, role = tid >> 7;

    {
        const uint4* sH = (const uint4*)g_WfH;
        const uint4* sL = (const uint4*)g_WfL;
        uint4* dH = (uint4*)WsH;
        uint4* dL = (uint4*)WsL;
        for (int idx = tid; idx < 272; idx += 256) { dH[idx] = sH[idx]; dL[idx] = sL[idx]; }
    }
    if (tid < 8) {
        float t = (float)(2 * tid) * (float)(-0.5756462732485115);
        freqs[tid] = (float)exp((double)t);
    }

    int a_r = lane & 15, a_c = (lane >> 4) * 8;
    int b_k = lane & 15, b_n = (lane >> 4) * 8;

    for (int t0 = blockIdx.x * 128; t0 < cnt; t0 += gridDim.x * 128) {
        __syncthreads();
        {
            int idx = t0 + e;
            bool valid = idx < cnt;
            int2 ji = g_fJI[valid ? idx : cnt - 1];
            int j = ji.x, i = ji.y;
            if (role == 0) { js[e] = valid ? j : -1; is_[e] = i; }
            float dpe = (float)(j - i);
            __nv_bfloat16* fH = FsH + e * 24;
            __nv_bfloat16* fL = FsL + e * 24;
            #pragma unroll
            for (int q = 0; q < 4; q++) {
                int kk = role * 4 + q;
                float s, c;
                sincosf(dpe * freqs[kk], &s, &c);
                split1(c, fH + kk, fL + kk);
                split1(s, fH + 8 + kk, fL + 8 + kk);
            }
        }
        __syncthreads();

        float acc[2][8][4];
        #pragma unroll
        for (int a_ = 0; a_ < 2; a_++)
            #pragma unroll
            for (int b_ = 0; b_ < 8; b_++)
                #pragma unroll
                for (int q = 0; q < 4; q++) acc[a_][b_][q] = 0.f;
        unsigned ah[2][4], al[2][4];
        #pragma unroll
        for (int mt = 0; mt < 2; mt++) {
            int row = warp_m * 32 + mt * 16 + a_r;
            LDSM4(ah[mt][0], ah[mt][1], ah[mt][2], ah[mt][3], sptr(FsH + row * 24 + a_c));
            LDSM4(al[mt][0], al[mt][1], al[mt][2], al[mt][3], sptr(FsL + row * 24 + a_c));
        }
        #pragma unroll
        for (int g = 0; g < 4; g++) {
            unsigned bh[4], bl[4];
            int nn = warp_n * 64 + g * 16 + b_n;
            LDSM4T(bh[0], bh[1], bh[2], bh[3], sptr(WsH + b_k * 136 + nn));
            LDSM4T(bl[0], bl[1], bl[2], bl[3], sptr(WsL + b_k * 136 + nn));
            #pragma unroll
            for (int mt = 0; mt < 2; mt++)
                #pragma unroll
                for (int t8 = 0; t8 < 2; t8++) {
                    int h = t8 * 2;
                    float* d = acc[mt][g * 2 + t8];
                    MMA16816(d, ah[mt][0], ah[mt][1], ah[mt][2], ah[mt][3], bh[h], bh[h + 1]);
                    MMA16816(d, ah[mt][0], ah[mt][1], ah[mt][2], ah[mt][3], bl[h], bl[h + 1]);
                    MMA16816(d, al[mt][0], al[mt][1], al[mt][2], al[mt][3], bh[h], bh[h + 1]);
                }
        }
        edge_scatter(acc, js, is_, warp_m, warp_n, lane);
    }
}

__global__ void __launch_bounds__(256) k_nodehead(const float* __restrict__ W0,
                                                  const float* __restrict__ b0,
                                                  const float* __restrict__ Wf,
                                                  const float* __restrict__ bf,
                                                  float* __restrict__ out2) {
    __shared__ float sW[4096];
    __shared__ float sb[32], sWf[64], sbf[2];
    int tid = threadIdx.x;
    for (int idx = tid; idx < 4096; idx += 256) sW[idx] = W0[idx];
    if (tid < 32) sb[tid] = b0[tid];
    if (tid < 64) sWf[tid] = Wf[tid];
    if (tid < 2) sbf[tid] = bf[tid];
    __syncthreads();
    int w = tid >> 5, lane = tid & 31;
    int n = blockIdx.x * 8 + w;
    if (n >= NN) return;
    const float* xr = g_x + n * HH;
    float acc = sb[lane];
    #pragma unroll 8
    for (int k = 0; k < 128; k++) acc += xr[k] * sW[k * 32 + lane];
    float xn = fmaxf(acc, 0.f);
    float v0 = xn * sWf[lane * 2], v1 = xn * sWf[lane * 2 + 1];
    #pragma unroll
    for (int off = 16; off > 0; off >>= 1) {
        v0 += __shfl_xor_sync(0xffffffffu, v0, off);
        v1 += __shfl_xor_sync(0xffffffffu, v1, off);
    }
    if (lane == 0) { out2[n * 2] = v0 + sbf[0]; out2[n * 2 + 1] = v1 + sbf[1]; }
}

extern "C" void kernel_launch(void* const* d_in, const int* in_sizes, int n_in,
                              void* d_out, int out_size) {
    const int* z = (const int*)d_in[0];
    const float* pos = (const float*)d_in[1];
    const float* posn = (const float*)d_in[2];
    const float* posc = (const float*)d_in[3];
    const float* bb = (const float*)d_in[4];
    const float* sc = (const float*)d_in[5];
    const float* esm = (const float*)d_in[6];
    const int* ei = (const int*)d_in[8];
    const float* W_emb = (const float*)d_in[9];
    const float* b_emb = (const float*)d_in[10];
    const float* W_esm = (const float*)d_in[11];
    const float* b_esm = (const float*)d_in[12];
    const float* W_edge = (const float*)d_in[13];
    const float* W_msg = (const float*)d_in[14];
    const float* W_upd = (const float*)d_in[15];
    const float* W_o0 = (const float*)d_in[16];
    const float* b_o0 = (const float*)d_in[17];
    const float* W_o1 = (const float*)d_in[18];
    const float* b_o1 = (const float*)d_in[19];
    const float* W_of = (const float*)d_in[20];
    const float* b_of = (const float*)d_in[21];
    const float* W_n0 = (const float*)d_in[22];
    const float* b_n0 = (const float*)d_in[23];
    const float* W_nf = (const float*)d_in[24];
    const float* b_nf = (const float*)d_in[25];
    float* out = (float*)d_out;

    const int GEMM_SMEM = 4 * 128 * 136 * 2;                     // 139264
    const int NEAR_SMEM = 4 * 128 * 136 * 2 + 2 * 128 * 4 + 32;  // 140320
    static cudaStream_t s1 = nullptr, s2 = nullptr;
    static cudaEvent_t evA, evB, evC, evE, evG, evF, evZ;
    if (!s1) {
        cudaStreamCreateWithFlags(&s1, cudaStreamNonBlocking);
        cudaStreamCreateWithFlags(&s2, cudaStreamNonBlocking);
        cudaEventCreateWithFlags(&evA, cudaEventDisableTiming);
        cudaEventCreateWithFlags(&evB, cudaEventDisableTiming);
        cudaEventCreateWithFlags(&evC, cudaEventDisableTiming);
        cudaEventCreateWithFlags(&evE, cudaEventDisableTiming);
        cudaEventCreateWithFlags(&evG, cudaEventDisableTiming);
        cudaEventCreateWithFlags(&evF, cudaEventDisableTiming);
        cudaEventCreateWithFlags(&evZ, cudaEventDisableTiming);
        cudaFuncSetAttribute(k_gemm0_tc, cudaFuncAttributeMaxDynamicSharedMemorySize, GEMM_SMEM);
        cudaFuncSetAttribute(k_gemm12_tc, cudaFuncAttributeMaxDynamicSharedMemorySize, GEMM_SMEM);
        cudaFuncSetAttribute(k_edge_near_tc, cudaFuncAttributeMaxDynamicSharedMemorySize, NEAR_SMEM);
    }

    // fork: esm on s1 overlaps the prologue; bulk zero on s2
    cudaEventRecord(evA, 0);
    cudaStreamWaitEvent(s1, evA, 0);
    k_esm_tc<<<391, 256, 0, s1>>>(esm, W_esm, b_esm);
    cudaEventRecord(evC, s1);                         // esm done

    cudaStreamWaitEvent(s2, evA, 0);
    k_zero_agg<<<6250, 256, 0, s2>>>();
    cudaEventRecord(evZ, s2);                         // agg zeroed

    k_zcnt<<<1, 1>>>();
    k_classify<<<3907, 256>>>(ei, pos);
    k_splitW<<<656, 128>>>(W_edge, W_msg, W_upd, W_o0, W_o1);
    k_embed<<<1563, 256>>>(z, bb, sc, W_emb, b_emb);
    cudaEventRecord(evB, 0);                          // prologue done

    // nodehead needs x (embed + esm); overlaps gemm0/edges
    cudaStreamWaitEvent(s1, evB, 0);
    k_nodehead<<<6250, 256, 0, s1>>>(W_n0, b_n0, W_nf, b_nf, out + NN);
    cudaEventRecord(evE, s1);

    cudaStreamWaitEvent(0, evC, 0);                   // gemm0 needs esm's half of x
    k_gemm0_tc<<<391, 256, GEMM_SMEM>>>();
    cudaEventRecord(evG, 0);                          // xm ready

    // far on s2 concurrent with near on stream 0
    cudaStreamWaitEvent(s2, evG, 0);
    k_edge_far_tc<<<444, 256, 0, s2>>>();
    cudaEventRecord(evF, s2);

    cudaStreamWaitEvent(0, evZ, 0);                   // near needs agg zeroed
    k_edge_near_tc<<<148, 256, NEAR_SMEM>>>(pos, posn, posc);
    cudaStreamWaitEvent(0, evF, 0);                   // join far before fused gemm+head
    k_gemm12_tc<<<391, 256, GEMM_SMEM>>>(b_o0, b_o1, W_of, b_of, out);
    cudaStreamWaitEvent(0, evE, 0);                   // join nodehead
}